// round 1
// baseline (speedup 1.0000x reference)
#include <cuda_runtime.h>
#include <math.h>

// ---------------- problem constants ----------------
#define BATCH 16
#define SEQ   512
#define SIN   384
#define SRES  129
#define WID   1024
#define HEADS 16
#define DHEAD 64
#define DFF   4096
#define NTOP  50
#define NGRP  7
#define MROWS (BATCH*SEQ)   // 8192

// ---------------- scratch (device globals, allocation-free) ----------------
__device__ float g_qkv[(size_t)MROWS * 3072];     // 96 MB
__device__ float g_ctx[(size_t)MROWS * WID];      // 32 MB (also reused for FF2 out)
__device__ float g_tmp[(size_t)MROWS * DFF];      // 128 MB (proj out + FF1 out)
__device__ float g_y  [(size_t)MROWS * WID];      // 32 MB
__device__ float g_hid[(size_t)MROWS * WID];      // 32 MB
__device__ float g_mp [NGRP * BATCH * WID];
__device__ float g_ue [NGRP * BATCH * WID];

// ---------------- SGEMM: C[M,N] = A[M,K] @ B[N,K]^T + bias (opt. GELU) ----------------
// 128x128 tile, BK=16, 256 threads, 8x8 per-thread
__global__ __launch_bounds__(256) void sgemm_bias(
    const float* __restrict__ A, const float* __restrict__ Bw,
    const float* __restrict__ bias, float* __restrict__ C,
    int Mm, int Nn, int Kk, int dogelu)
{
    __shared__ float As[16][128];
    __shared__ float Bs[16][128];

    const int tid = threadIdx.x;
    const int tx = tid & 15;        // 0..15 -> N
    const int ty = tid >> 4;        // 0..15 -> M
    const int m0 = blockIdx.y * 128;
    const int n0 = blockIdx.x * 128;

    float acc[8][8];
    #pragma unroll
    for (int i = 0; i < 8; i++)
        #pragma unroll
        for (int j = 0; j < 8; j++) acc[i][j] = 0.0f;

    const int lr = tid >> 2;        // 0..63
    const int lc = (tid & 3) * 4;   // k offset 0,4,8,12
    const float* Ag = A  + (size_t)(m0 + lr) * Kk + lc;
    const float* Bg = Bw + (size_t)(n0 + lr) * Kk + lc;
    const size_t strideA = (size_t)64 * Kk;

    for (int k0 = 0; k0 < Kk; k0 += 16) {
        float4 a0 = *(const float4*)(Ag + k0);
        float4 a1 = *(const float4*)(Ag + strideA + k0);
        float4 b0 = *(const float4*)(Bg + k0);
        float4 b1 = *(const float4*)(Bg + strideA + k0);

        As[lc+0][lr] = a0.x; As[lc+1][lr] = a0.y; As[lc+2][lr] = a0.z; As[lc+3][lr] = a0.w;
        As[lc+0][lr+64] = a1.x; As[lc+1][lr+64] = a1.y; As[lc+2][lr+64] = a1.z; As[lc+3][lr+64] = a1.w;
        Bs[lc+0][lr] = b0.x; Bs[lc+1][lr] = b0.y; Bs[lc+2][lr] = b0.z; Bs[lc+3][lr] = b0.w;
        Bs[lc+0][lr+64] = b1.x; Bs[lc+1][lr+64] = b1.y; Bs[lc+2][lr+64] = b1.z; Bs[lc+3][lr+64] = b1.w;
        __syncthreads();

        #pragma unroll
        for (int kk = 0; kk < 16; kk++) {
            float af[8], bf[8];
            *(float4*)&af[0] = *(const float4*)&As[kk][ty*8];
            *(float4*)&af[4] = *(const float4*)&As[kk][ty*8+4];
            *(float4*)&bf[0] = *(const float4*)&Bs[kk][tx*8];
            *(float4*)&bf[4] = *(const float4*)&Bs[kk][tx*8+4];
            #pragma unroll
            for (int i = 0; i < 8; i++)
                #pragma unroll
                for (int j = 0; j < 8; j++)
                    acc[i][j] = fmaf(af[i], bf[j], acc[i][j]);
        }
        __syncthreads();
    }

    float bv[8];
    *(float4*)&bv[0] = *(const float4*)(bias + n0 + tx*8);
    *(float4*)&bv[4] = *(const float4*)(bias + n0 + tx*8 + 4);

    #pragma unroll
    for (int i = 0; i < 8; i++) {
        size_t row = (size_t)(m0 + ty*8 + i);
        float* Cp = C + row * Nn + n0 + tx*8;
        float o[8];
        #pragma unroll
        for (int j = 0; j < 8; j++) {
            float v = acc[i][j] + bv[j];
            if (dogelu) v = 0.5f * v * (1.0f + erff(v * 0.70710678118654752f));
            o[j] = v;
        }
        *(float4*)&Cp[0] = *(float4*)&o[0];
        *(float4*)&Cp[4] = *(float4*)&o[4];
    }
}

// ---------------- attention: per (b,h), 1 thread per q row, online softmax ----------------
#define QT 128
#define KT 64
__global__ __launch_bounds__(128) void attn_kernel(
    const float* __restrict__ qkv, float* __restrict__ ctx)
{
    const int bh = blockIdx.y;
    const int b = bh >> 4, h = bh & 15;
    const int q0 = blockIdx.x * QT;
    const int tid = threadIdx.x;

    __shared__ float Ks[KT][DHEAD];
    __shared__ float Vs[KT][DHEAD];

    float q[DHEAD], acc[DHEAD];
    const float* qp = qkv + (size_t)(b*SEQ + q0 + tid) * 3072 + h*DHEAD;
    #pragma unroll
    for (int i = 0; i < 16; i++) *(float4*)&q[i*4] = *(const float4*)(qp + i*4);
    #pragma unroll
    for (int d = 0; d < DHEAD; d++) acc[d] = 0.0f;

    float mx = -1e30f, l = 0.0f;

    for (int k0 = 0; k0 < SEQ; k0 += KT) {
        #pragma unroll
        for (int i = 0; i < 8; i++) {
            int idx = i*128 + tid;
            int r = idx >> 4, c4 = (idx & 15) * 4;
            const float* base = qkv + (size_t)(b*SEQ + k0 + r) * 3072 + h*DHEAD + c4;
            *(float4*)&Ks[r][c4] = *(const float4*)(base + 1024);
            *(float4*)&Vs[r][c4] = *(const float4*)(base + 2048);
        }
        __syncthreads();

        for (int j = 0; j < KT; j++) {
            float s = 0.0f;
            #pragma unroll
            for (int d = 0; d < DHEAD; d++) s = fmaf(q[d], Ks[j][d], s);
            s *= 0.125f;
            float m2 = fmaxf(mx, s);
            float corr = __expf(mx - m2);
            float p = __expf(s - m2);
            l = l * corr + p;
            #pragma unroll
            for (int d = 0; d < DHEAD; d++) acc[d] = fmaf(acc[d], corr, p * Vs[j][d]);
            mx = m2;
        }
        __syncthreads();
    }

    float inv = 1.0f / l;
    float* op = ctx + (size_t)(b*SEQ + q0 + tid) * WID + h*DHEAD;
    #pragma unroll
    for (int i = 0; i < 16; i++) {
        float4 v;
        v.x = acc[i*4+0]*inv; v.y = acc[i*4+1]*inv; v.z = acc[i*4+2]*inv; v.w = acc[i*4+3]*inv;
        *(float4*)(op + i*4) = v;
    }
}

// ---------------- residual add + LayerNorm (row = 1024) ----------------
__global__ __launch_bounds__(256) void add_ln_kernel(
    const float* __restrict__ resid, const float* __restrict__ x,
    const float* __restrict__ gg, const float* __restrict__ bb,
    float* __restrict__ out)
{
    __shared__ float2 sm[8];
    const size_t row = blockIdx.x;
    const int tid = threadIdx.x;

    float4 r = *(const float4*)(resid + row*WID + tid*4);
    float4 v = *(const float4*)(x     + row*WID + tid*4);
    float4 t;
    t.x = r.x + v.x; t.y = r.y + v.y; t.z = r.z + v.z; t.w = r.w + v.w;

    float s = t.x + t.y + t.z + t.w;
    float qq = t.x*t.x + t.y*t.y + t.z*t.z + t.w*t.w;

    int lane = tid & 31, warp = tid >> 5;
    #pragma unroll
    for (int o = 16; o > 0; o >>= 1) {
        s  += __shfl_down_sync(0xffffffffu, s,  o);
        qq += __shfl_down_sync(0xffffffffu, qq, o);
    }
    if (lane == 0) sm[warp] = make_float2(s, qq);
    __syncthreads();
    if (warp == 0) {
        float2 w2 = (lane < 8) ? sm[lane] : make_float2(0.f, 0.f);
        #pragma unroll
        for (int o = 4; o > 0; o >>= 1) {
            w2.x += __shfl_down_sync(0xffffffffu, w2.x, o);
            w2.y += __shfl_down_sync(0xffffffffu, w2.y, o);
        }
        if (lane == 0) sm[0] = w2;
    }
    __syncthreads();
    float mean = sm[0].x * (1.0f/WID);
    float var  = sm[0].y * (1.0f/WID) - mean*mean;
    float rstd = rsqrtf(var + 1e-5f);

    float4 g4 = *(const float4*)(gg + tid*4);
    float4 b4 = *(const float4*)(bb + tid*4);
    float4 o;
    o.x = (t.x - mean)*rstd*g4.x + b4.x;
    o.y = (t.y - mean)*rstd*g4.y + b4.y;
    o.z = (t.z - mean)*rstd*g4.z + b4.z;
    o.w = (t.w - mean)*rstd*g4.w + b4.w;
    *(float4*)(out + row*WID + tid*4) = o;
}

// ---------------- masked max-pool over sequence ----------------
__global__ __launch_bounds__(256) void maxpool_kernel(
    const float* __restrict__ hidden, const int* __restrict__ in_ids,
    const int* __restrict__ resp_ids, float* __restrict__ mp)
{
    const int g = blockIdx.x;   // 0..6
    const int b = blockIdx.y;   // 0..15
    const int tid = threadIdx.x;
    __shared__ unsigned char flag[SEQ];

    for (int s = tid; s < SEQ; s += 256) {
        bool f = false;
        if (g < 6) { if (s < SIN) f = (in_ids[b*SIN + s] == g + 1); }
        else       { if (s >= SIN) f = (resp_ids[b*SRES + (s - SIN + 1)] == 1); }
        flag[s] = f ? 1 : 0;
    }
    __syncthreads();

    const int w = tid * 4;
    float4 vm = make_float4(0.f, 0.f, 0.f, 0.f);   // max includes 0 baseline (jnp.where)
    for (int s = 0; s < SEQ; s++) {
        if (flag[s]) {
            float4 hv = *(const float4*)(hidden + (size_t)(b*SEQ + s)*WID + w);
            vm.x = fmaxf(vm.x, hv.x); vm.y = fmaxf(vm.y, hv.y);
            vm.z = fmaxf(vm.z, hv.z); vm.w = fmaxf(vm.w, hv.w);
        }
    }
    *(float4*)(mp + (size_t)(g*BATCH + b)*WID + w) = vm;
}

// ---------------- topic: logits -> softmax -> table gather ----------------
__global__ __launch_bounds__(256) void topic_kernel(
    const float* __restrict__ mp, const float* __restrict__ tw,
    const float* __restrict__ tb, const float* __restrict__ table,
    float* __restrict__ ue)
{
    const int gb = blockIdx.x;   // 0..111
    const int tid = threadIdx.x;
    __shared__ float mpv[WID];
    __shared__ float probs[NTOP];
    __shared__ float logits[NTOP];

    *(float4*)&mpv[tid*4] = *(const float4*)(mp + (size_t)gb*WID + tid*4);
    __syncthreads();

    const int warp = tid >> 5, lane = tid & 31;
    for (int t = warp; t < NTOP; t += 8) {
        const float* wr = tw + (size_t)t * WID;
        float s = 0.0f;
        for (int w = lane; w < WID; w += 32) s = fmaf(mpv[w], wr[w], s);
        #pragma unroll
        for (int o = 16; o > 0; o >>= 1) s += __shfl_down_sync(0xffffffffu, s, o);
        if (lane == 0) logits[t] = s + tb[t];
    }
    __syncthreads();

    if (tid == 0) {
        float m = -1e30f;
        for (int t = 0; t < NTOP; t++) m = fmaxf(m, logits[t]);
        float sum = 0.0f;
        for (int t = 0; t < NTOP; t++) { float e = expf(logits[t] - m); probs[t] = e; sum += e; }
        float inv = 1.0f / sum;
        for (int t = 0; t < NTOP; t++) probs[t] *= inv;
    }
    __syncthreads();

    const int w = tid * 4;
    float4 a = make_float4(0.f, 0.f, 0.f, 0.f);
    for (int t = 0; t < NTOP; t++) {
        float p = probs[t];
        float4 tv = *(const float4*)(table + (size_t)t*WID + w);
        a.x = fmaf(p, tv.x, a.x); a.y = fmaf(p, tv.y, a.y);
        a.z = fmaf(p, tv.z, a.z); a.w = fmaf(p, tv.w, a.w);
    }
    *(float4*)(ue + (size_t)gb*WID + w) = a;
}

// ---------------- final scatter-add: out = X + mult * ue[group] ----------------
__global__ __launch_bounds__(256) void out_kernel(
    const float* __restrict__ X, const int* __restrict__ in_ids,
    const int* __restrict__ resp_ids, const float* __restrict__ ue,
    float* __restrict__ out)
{
    const int bs = blockIdx.x;
    const int b = bs >> 9, s = bs & 511;
    int g = -1; float c = 0.0f;
    if (s < SIN) {
        int v = in_ids[b*SIN + s];
        if (v > 0)      { g = v - 1;   c = 1.0f; }
        else if (v < 0) { g = -v - 1;  c = 2.0f; }
    } else {
        int v = resp_ids[b*SRES + (s - SIN + 1)];
        if (v == 1)       { g = 6; c = 1.0f; }
        else if (v == -1) { g = 6; c = 2.0f; }
    }
    const int w = threadIdx.x * 4;
    float4 xv = *(const float4*)(X + (size_t)bs*WID + w);
    if (g >= 0) {
        float4 u = *(const float4*)(ue + (size_t)(g*BATCH + b)*WID + w);
        xv.x = fmaf(c, u.x, xv.x); xv.y = fmaf(c, u.y, xv.y);
        xv.z = fmaf(c, u.z, xv.z); xv.w = fmaf(c, u.w, xv.w);
    }
    *(float4*)(out + (size_t)bs*WID + w) = xv;
}

// ---------------- launch ----------------
extern "C" void kernel_launch(void* const* d_in, const int* in_sizes, int n_in,
                              void* d_out, int out_size)
{
    const float* X       = (const float*)d_in[0];
    const int*   in_ids  = (const int*)  d_in[1];
    const int*   resp_ids= (const int*)  d_in[2];
    const float* Wqkv    = (const float*)d_in[3];
    const float* bqkv    = (const float*)d_in[4];
    const float* Wo      = (const float*)d_in[5];
    const float* bo      = (const float*)d_in[6];
    const float* ln1g    = (const float*)d_in[7];
    const float* ln1b    = (const float*)d_in[8];
    const float* W1      = (const float*)d_in[9];
    const float* b1      = (const float*)d_in[10];
    const float* W2      = (const float*)d_in[11];
    const float* b2      = (const float*)d_in[12];
    const float* ln2g    = (const float*)d_in[13];
    const float* ln2b    = (const float*)d_in[14];
    const float* tw      = (const float*)d_in[15];
    const float* tb      = (const float*)d_in[16];
    const float* table   = (const float*)d_in[17];
    float* out = (float*)d_out;

    float *qkv, *ctx, *tmp, *y, *hid, *mp, *ue;
    cudaGetSymbolAddress((void**)&qkv, g_qkv);
    cudaGetSymbolAddress((void**)&ctx, g_ctx);
    cudaGetSymbolAddress((void**)&tmp, g_tmp);
    cudaGetSymbolAddress((void**)&y,   g_y);
    cudaGetSymbolAddress((void**)&hid, g_hid);
    cudaGetSymbolAddress((void**)&mp,  g_mp);
    cudaGetSymbolAddress((void**)&ue,  g_ue);

    // 1. QKV = X @ Wqkv^T + bqkv
    sgemm_bias<<<dim3(3072/128, MROWS/128), 256>>>(X, Wqkv, bqkv, qkv, MROWS, 3072, 1024, 0);
    // 2. attention
    attn_kernel<<<dim3(SEQ/QT, BATCH*HEADS), 128>>>(qkv, ctx);
    // 3. proj
    sgemm_bias<<<dim3(WID/128, MROWS/128), 256>>>(ctx, Wo, bo, tmp, MROWS, WID, 1024, 0);
    // 4. y = LN(X + proj)
    add_ln_kernel<<<MROWS, 256>>>(X, tmp, ln1g, ln1b, y);
    // 5. FF1 + GELU
    sgemm_bias<<<dim3(DFF/128, MROWS/128), 256>>>(y, W1, b1, tmp, MROWS, DFF, 1024, 1);
    // 6. FF2
    sgemm_bias<<<dim3(WID/128, MROWS/128), 256>>>(tmp, W2, b2, ctx, MROWS, WID, DFF, 0);
    // 7. hidden = LN(y + FF2)
    add_ln_kernel<<<MROWS, 256>>>(y, ctx, ln2g, ln2b, hid);
    // 8. masked max-pool per (group, batch)
    maxpool_kernel<<<dim3(NGRP, BATCH), 256>>>(hid, in_ids, resp_ids, mp);
    // 9. topic softmax + gather
    topic_kernel<<<NGRP*BATCH, 256>>>(mp, tw, tb, table, ue);
    // 10. final output
    out_kernel<<<MROWS, 256>>>(X, in_ids, resp_ids, ue, out);
}

// round 2
// speedup vs baseline: 2.8445x; 2.8445x over previous
#include <cuda_runtime.h>
#include <math.h>
#include <cstdint>

// ---------------- problem constants ----------------
#define BATCH 16
#define SEQ   512
#define SIN   384
#define SRES  129
#define WID   1024
#define HEADS 16
#define DHEAD 64
#define DFF   4096
#define NTOP  50
#define NGRP  7
#define MROWS (BATCH*SEQ)   // 8192

// ---------------- scratch (device globals, allocation-free) ----------------
__device__ float g_qkv[(size_t)MROWS * 3072];     // 96 MB
__device__ float g_ctx[(size_t)MROWS * WID];      // 32 MB
__device__ float g_tmp[(size_t)MROWS * DFF];      // 128 MB
__device__ float g_y  [(size_t)MROWS * WID];      // 32 MB
__device__ float g_hid[(size_t)MROWS * WID];      // 32 MB
__device__ float g_mp [NGRP * BATCH * WID];
__device__ float g_ue [NGRP * BATCH * WID];

// ================= TF32 tensor-core GEMM =================
// C[M,N] = A[M,K] @ B[N,K]^T + bias, optional exact GELU.
// 128x128x32 tile, 256 threads (8 warps, 2x4), warp tile 64x32 (4x4 m16n8k8).
// 3-stage cp.async pipeline. fp32 bits passed directly as tf32 operands.
#define BM 128
#define BN 128
#define BK 32
#define NSTAGE 3
#define LDSW (BK + 4)          // 36 floats per smem row -> conflict-free frags
#define STAGE_F (BM * LDSW)    // floats per stage per operand

__device__ __forceinline__ void cpa16(float* dst, const float* src) {
    uint32_t d = (uint32_t)__cvta_generic_to_shared(dst);
    asm volatile("cp.async.cg.shared.global [%0], [%1], 16;" :: "r"(d), "l"(src));
}

__global__ __launch_bounds__(256) void mma_gemm(
    const float* __restrict__ A, const float* __restrict__ Bw,
    const float* __restrict__ bias, float* __restrict__ C,
    int M, int N, int K, int dogelu)
{
    extern __shared__ float smbuf[];
    float* As = smbuf;                       // NSTAGE * STAGE_F
    float* Bs = smbuf + NSTAGE * STAGE_F;

    const int tid  = threadIdx.x;
    const int m0   = blockIdx.y * BM;
    const int n0   = blockIdx.x * BN;
    const int warp = tid >> 5, lane = tid & 31;
    const int g    = lane >> 2, tig = lane & 3;
    const int mw   = (warp >> 2) * 64;   // 0 or 64
    const int nw   = (warp & 3) * 32;    // 0,32,64,96

    float acc[4][4][4];
    #pragma unroll
    for (int mi = 0; mi < 4; mi++)
        #pragma unroll
        for (int ni = 0; ni < 4; ni++)
            #pragma unroll
            for (int r = 0; r < 4; r++) acc[mi][ni][r] = 0.0f;

    const int kiters = K / BK;

    // per-thread copy coords: 1024 16B-chunks per operand tile, 4 per thread
    const int crow0 = tid >> 1;            // used via c = tid + i*256
    (void)crow0;

    // ---- prologue: stages 0,1 ----
    #pragma unroll
    for (int s = 0; s < NSTAGE - 1; s++) {
        const int k0 = s * BK;
        #pragma unroll
        for (int i = 0; i < 4; i++) {
            int c = tid + i * 256;
            int row = c >> 3, kc = (c & 7) * 4;
            cpa16(As + s * STAGE_F + row * LDSW + kc, A  + (size_t)(m0 + row) * K + k0 + kc);
            cpa16(Bs + s * STAGE_F + row * LDSW + kc, Bw + (size_t)(n0 + row) * K + k0 + kc);
        }
        asm volatile("cp.async.commit_group;");
    }

    for (int kt = 0; kt < kiters; kt++) {
        // prefetch stage kt+2
        if (kt + NSTAGE - 1 < kiters) {
            const int s = (kt + NSTAGE - 1) % NSTAGE;
            const int k0 = (kt + NSTAGE - 1) * BK;
            #pragma unroll
            for (int i = 0; i < 4; i++) {
                int c = tid + i * 256;
                int row = c >> 3, kc = (c & 7) * 4;
                cpa16(As + s * STAGE_F + row * LDSW + kc, A  + (size_t)(m0 + row) * K + k0 + kc);
                cpa16(Bs + s * STAGE_F + row * LDSW + kc, Bw + (size_t)(n0 + row) * K + k0 + kc);
            }
        }
        asm volatile("cp.async.commit_group;");
        asm volatile("cp.async.wait_group %0;" :: "n"(NSTAGE - 1));
        __syncthreads();

        const float* as = As + (kt % NSTAGE) * STAGE_F;
        const float* bs = Bs + (kt % NSTAGE) * STAGE_F;

        #pragma unroll
        for (int kk = 0; kk < BK; kk += 8) {
            uint32_t af[4][4], bf[4][2];
            #pragma unroll
            for (int mi = 0; mi < 4; mi++) {
                const float* p  = as + (mw + mi * 16 + g) * LDSW + kk + tig;
                const float* p2 = p + 8 * LDSW;
                af[mi][0] = __float_as_uint(p[0]);
                af[mi][2] = __float_as_uint(p[4]);
                af[mi][1] = __float_as_uint(p2[0]);
                af[mi][3] = __float_as_uint(p2[4]);
            }
            #pragma unroll
            for (int ni = 0; ni < 4; ni++) {
                const float* p = bs + (nw + ni * 8 + g) * LDSW + kk + tig;
                bf[ni][0] = __float_as_uint(p[0]);
                bf[ni][1] = __float_as_uint(p[4]);
            }
            #pragma unroll
            for (int mi = 0; mi < 4; mi++)
                #pragma unroll
                for (int ni = 0; ni < 4; ni++) {
                    asm volatile(
                        "mma.sync.aligned.m16n8k8.row.col.f32.tf32.tf32.f32 "
                        "{%0,%1,%2,%3}, {%4,%5,%6,%7}, {%8,%9}, {%0,%1,%2,%3};"
                        : "+f"(acc[mi][ni][0]), "+f"(acc[mi][ni][1]),
                          "+f"(acc[mi][ni][2]), "+f"(acc[mi][ni][3])
                        : "r"(af[mi][0]), "r"(af[mi][1]), "r"(af[mi][2]), "r"(af[mi][3]),
                          "r"(bf[ni][0]), "r"(bf[ni][1]));
                }
        }
        __syncthreads();
    }

    // ---- epilogue ----
    #pragma unroll
    for (int ni = 0; ni < 4; ni++) {
        const int cc = n0 + nw + ni * 8 + 2 * tig;
        const float bv0 = bias[cc], bv1 = bias[cc + 1];
        #pragma unroll
        for (int mi = 0; mi < 4; mi++) {
            const int r0 = m0 + mw + mi * 16 + g;
            float v00 = acc[mi][ni][0] + bv0;
            float v01 = acc[mi][ni][1] + bv1;
            float v10 = acc[mi][ni][2] + bv0;
            float v11 = acc[mi][ni][3] + bv1;
            if (dogelu) {
                v00 = 0.5f * v00 * (1.0f + erff(v00 * 0.70710678118654752f));
                v01 = 0.5f * v01 * (1.0f + erff(v01 * 0.70710678118654752f));
                v10 = 0.5f * v10 * (1.0f + erff(v10 * 0.70710678118654752f));
                v11 = 0.5f * v11 * (1.0f + erff(v11 * 0.70710678118654752f));
            }
            *(float2*)(C + (size_t)r0 * N + cc)       = make_float2(v00, v01);
            *(float2*)(C + (size_t)(r0 + 8) * N + cc) = make_float2(v10, v11);
        }
    }
}

// ---------------- attention: per (b,h), 1 thread per q row, online softmax ----------------
#define QT 128
#define KT 64
__global__ __launch_bounds__(128) void attn_kernel(
    const float* __restrict__ qkv, float* __restrict__ ctx)
{
    const int bh = blockIdx.y;
    const int b = bh >> 4, h = bh & 15;
    const int q0 = blockIdx.x * QT;
    const int tid = threadIdx.x;

    __shared__ float Ks[KT][DHEAD];
    __shared__ float Vs[KT][DHEAD];

    float q[DHEAD], acc[DHEAD];
    const float* qp = qkv + (size_t)(b*SEQ + q0 + tid) * 3072 + h*DHEAD;
    #pragma unroll
    for (int i = 0; i < 16; i++) *(float4*)&q[i*4] = *(const float4*)(qp + i*4);
    #pragma unroll
    for (int d = 0; d < DHEAD; d++) acc[d] = 0.0f;

    float mx = -1e30f, l = 0.0f;

    for (int k0 = 0; k0 < SEQ; k0 += KT) {
        #pragma unroll
        for (int i = 0; i < 8; i++) {
            int idx = i*128 + tid;
            int r = idx >> 4, c4 = (idx & 15) * 4;
            const float* base = qkv + (size_t)(b*SEQ + k0 + r) * 3072 + h*DHEAD + c4;
            *(float4*)&Ks[r][c4] = *(const float4*)(base + 1024);
            *(float4*)&Vs[r][c4] = *(const float4*)(base + 2048);
        }
        __syncthreads();

        for (int j = 0; j < KT; j++) {
            float s = 0.0f;
            #pragma unroll
            for (int d = 0; d < DHEAD; d++) s = fmaf(q[d], Ks[j][d], s);
            s *= 0.125f;
            float m2 = fmaxf(mx, s);
            float corr = __expf(mx - m2);
            float p = __expf(s - m2);
            l = l * corr + p;
            #pragma unroll
            for (int d = 0; d < DHEAD; d++) acc[d] = fmaf(acc[d], corr, p * Vs[j][d]);
            mx = m2;
        }
        __syncthreads();
    }

    float inv = 1.0f / l;
    float* op = ctx + (size_t)(b*SEQ + q0 + tid) * WID + h*DHEAD;
    #pragma unroll
    for (int i = 0; i < 16; i++) {
        float4 v;
        v.x = acc[i*4+0]*inv; v.y = acc[i*4+1]*inv; v.z = acc[i*4+2]*inv; v.w = acc[i*4+3]*inv;
        *(float4*)(op + i*4) = v;
    }
}

// ---------------- residual add + LayerNorm (row = 1024) ----------------
__global__ __launch_bounds__(256) void add_ln_kernel(
    const float* __restrict__ resid, const float* __restrict__ x,
    const float* __restrict__ gg, const float* __restrict__ bb,
    float* __restrict__ out)
{
    __shared__ float2 sm[8];
    const size_t row = blockIdx.x;
    const int tid = threadIdx.x;

    float4 r = *(const float4*)(resid + row*WID + tid*4);
    float4 v = *(const float4*)(x     + row*WID + tid*4);
    float4 t;
    t.x = r.x + v.x; t.y = r.y + v.y; t.z = r.z + v.z; t.w = r.w + v.w;

    float s = t.x + t.y + t.z + t.w;
    float qq = t.x*t.x + t.y*t.y + t.z*t.z + t.w*t.w;

    int lane = tid & 31, warp = tid >> 5;
    #pragma unroll
    for (int o = 16; o > 0; o >>= 1) {
        s  += __shfl_down_sync(0xffffffffu, s,  o);
        qq += __shfl_down_sync(0xffffffffu, qq, o);
    }
    if (lane == 0) sm[warp] = make_float2(s, qq);
    __syncthreads();
    if (warp == 0) {
        float2 w2 = (lane < 8) ? sm[lane] : make_float2(0.f, 0.f);
        #pragma unroll
        for (int o = 4; o > 0; o >>= 1) {
            w2.x += __shfl_down_sync(0xffffffffu, w2.x, o);
            w2.y += __shfl_down_sync(0xffffffffu, w2.y, o);
        }
        if (lane == 0) sm[0] = w2;
    }
    __syncthreads();
    float mean = sm[0].x * (1.0f/WID);
    float var  = sm[0].y * (1.0f/WID) - mean*mean;
    float rstd = rsqrtf(var + 1e-5f);

    float4 g4 = *(const float4*)(gg + tid*4);
    float4 b4 = *(const float4*)(bb + tid*4);
    float4 o;
    o.x = (t.x - mean)*rstd*g4.x + b4.x;
    o.y = (t.y - mean)*rstd*g4.y + b4.y;
    o.z = (t.z - mean)*rstd*g4.z + b4.z;
    o.w = (t.w - mean)*rstd*g4.w + b4.w;
    *(float4*)(out + row*WID + tid*4) = o;
}

// ---------------- masked max-pool over sequence ----------------
__global__ __launch_bounds__(256) void maxpool_kernel(
    const float* __restrict__ hidden, const int* __restrict__ in_ids,
    const int* __restrict__ resp_ids, float* __restrict__ mp)
{
    const int g = blockIdx.x;   // 0..6
    const int b = blockIdx.y;   // 0..15
    const int tid = threadIdx.x;
    __shared__ unsigned char flag[SEQ];

    for (int s = tid; s < SEQ; s += 256) {
        bool f = false;
        if (g < 6) { if (s < SIN) f = (in_ids[b*SIN + s] == g + 1); }
        else       { if (s >= SIN) f = (resp_ids[b*SRES + (s - SIN + 1)] == 1); }
        flag[s] = f ? 1 : 0;
    }
    __syncthreads();

    const int w = tid * 4;
    float4 vm = make_float4(0.f, 0.f, 0.f, 0.f);
    for (int s = 0; s < SEQ; s++) {
        if (flag[s]) {
            float4 hv = *(const float4*)(hidden + (size_t)(b*SEQ + s)*WID + w);
            vm.x = fmaxf(vm.x, hv.x); vm.y = fmaxf(vm.y, hv.y);
            vm.z = fmaxf(vm.z, hv.z); vm.w = fmaxf(vm.w, hv.w);
        }
    }
    *(float4*)(mp + (size_t)(g*BATCH + b)*WID + w) = vm;
}

// ---------------- topic: logits -> softmax -> table gather ----------------
__global__ __launch_bounds__(256) void topic_kernel(
    const float* __restrict__ mp, const float* __restrict__ tw,
    const float* __restrict__ tb, const float* __restrict__ table,
    float* __restrict__ ue)
{
    const int gb = blockIdx.x;
    const int tid = threadIdx.x;
    __shared__ float mpv[WID];
    __shared__ float probs[NTOP];
    __shared__ float logits[NTOP];

    *(float4*)&mpv[tid*4] = *(const float4*)(mp + (size_t)gb*WID + tid*4);
    __syncthreads();

    const int warp = tid >> 5, lane = tid & 31;
    for (int t = warp; t < NTOP; t += 8) {
        const float* wr = tw + (size_t)t * WID;
        float s = 0.0f;
        for (int w = lane; w < WID; w += 32) s = fmaf(mpv[w], wr[w], s);
        #pragma unroll
        for (int o = 16; o > 0; o >>= 1) s += __shfl_down_sync(0xffffffffu, s, o);
        if (lane == 0) logits[t] = s + tb[t];
    }
    __syncthreads();

    if (tid == 0) {
        float m = -1e30f;
        for (int t = 0; t < NTOP; t++) m = fmaxf(m, logits[t]);
        float sum = 0.0f;
        for (int t = 0; t < NTOP; t++) { float e = expf(logits[t] - m); probs[t] = e; sum += e; }
        float inv = 1.0f / sum;
        for (int t = 0; t < NTOP; t++) probs[t] *= inv;
    }
    __syncthreads();

    const int w = tid * 4;
    float4 a = make_float4(0.f, 0.f, 0.f, 0.f);
    for (int t = 0; t < NTOP; t++) {
        float p = probs[t];
        float4 tv = *(const float4*)(table + (size_t)t*WID + w);
        a.x = fmaf(p, tv.x, a.x); a.y = fmaf(p, tv.y, a.y);
        a.z = fmaf(p, tv.z, a.z); a.w = fmaf(p, tv.w, a.w);
    }
    *(float4*)(ue + (size_t)gb*WID + w) = a;
}

// ---------------- final scatter-add: out = X + mult * ue[group] ----------------
__global__ __launch_bounds__(256) void out_kernel(
    const float* __restrict__ X, const int* __restrict__ in_ids,
    const int* __restrict__ resp_ids, const float* __restrict__ ue,
    float* __restrict__ out)
{
    const int bs = blockIdx.x;
    const int b = bs >> 9, s = bs & 511;
    int g = -1; float c = 0.0f;
    if (s < SIN) {
        int v = in_ids[b*SIN + s];
        if (v > 0)      { g = v - 1;   c = 1.0f; }
        else if (v < 0) { g = -v - 1;  c = 2.0f; }
    } else {
        int v = resp_ids[b*SRES + (s - SIN + 1)];
        if (v == 1)       { g = 6; c = 1.0f; }
        else if (v == -1) { g = 6; c = 2.0f; }
    }
    const int w = threadIdx.x * 4;
    float4 xv = *(const float4*)(X + (size_t)bs*WID + w);
    if (g >= 0) {
        float4 u = *(const float4*)(ue + (size_t)(g*BATCH + b)*WID + w);
        xv.x = fmaf(c, u.x, xv.x); xv.y = fmaf(c, u.y, xv.y);
        xv.z = fmaf(c, u.z, xv.z); xv.w = fmaf(c, u.w, xv.w);
    }
    *(float4*)(out + (size_t)bs*WID + w) = xv;
}

// ---------------- launch ----------------
extern "C" void kernel_launch(void* const* d_in, const int* in_sizes, int n_in,
                              void* d_out, int out_size)
{
    const float* X       = (const float*)d_in[0];
    const int*   in_ids  = (const int*)  d_in[1];
    const int*   resp_ids= (const int*)  d_in[2];
    const float* Wqkv    = (const float*)d_in[3];
    const float* bqkv    = (const float*)d_in[4];
    const float* Wo      = (const float*)d_in[5];
    const float* bo      = (const float*)d_in[6];
    const float* ln1g    = (const float*)d_in[7];
    const float* ln1b    = (const float*)d_in[8];
    const float* W1      = (const float*)d_in[9];
    const float* b1      = (const float*)d_in[10];
    const float* W2      = (const float*)d_in[11];
    const float* b2      = (const float*)d_in[12];
    const float* ln2g    = (const float*)d_in[13];
    const float* ln2b    = (const float*)d_in[14];
    const float* tw      = (const float*)d_in[15];
    const float* tb      = (const float*)d_in[16];
    const float* table   = (const float*)d_in[17];
    float* out = (float*)d_out;

    float *qkv, *ctx, *tmp, *y, *hid, *mp, *ue;
    cudaGetSymbolAddress((void**)&qkv, g_qkv);
    cudaGetSymbolAddress((void**)&ctx, g_ctx);
    cudaGetSymbolAddress((void**)&tmp, g_tmp);
    cudaGetSymbolAddress((void**)&y,   g_y);
    cudaGetSymbolAddress((void**)&hid, g_hid);
    cudaGetSymbolAddress((void**)&mp,  g_mp);
    cudaGetSymbolAddress((void**)&ue,  g_ue);

    const int smem = NSTAGE * STAGE_F * 2 * sizeof(float);  // 110,592 B
    cudaFuncSetAttribute(mma_gemm, cudaFuncAttributeMaxDynamicSharedMemorySize, smem);

    // 1. QKV = X @ Wqkv^T + bqkv
    mma_gemm<<<dim3(3072/BN, MROWS/BM), 256, smem>>>(X, Wqkv, bqkv, qkv, MROWS, 3072, 1024, 0);
    // 2. attention
    attn_kernel<<<dim3(SEQ/QT, BATCH*HEADS), 128>>>(qkv, ctx);
    // 3. proj
    mma_gemm<<<dim3(WID/BN, MROWS/BM), 256, smem>>>(ctx, Wo, bo, tmp, MROWS, WID, 1024, 0);
    // 4. y = LN(X + proj)
    add_ln_kernel<<<MROWS, 256>>>(X, tmp, ln1g, ln1b, y);
    // 5. FF1 + GELU
    mma_gemm<<<dim3(DFF/BN, MROWS/BM), 256, smem>>>(y, W1, b1, tmp, MROWS, DFF, 1024, 1);
    // 6. FF2
    mma_gemm<<<dim3(WID/BN, MROWS/BM), 256, smem>>>(tmp, W2, b2, ctx, MROWS, WID, 4096, 0);
    // 7. hidden = LN(y + FF2)
    add_ln_kernel<<<MROWS, 256>>>(y, ctx, ln2g, ln2b, hid);
    // 8. masked max-pool per (group, batch)
    maxpool_kernel<<<dim3(NGRP, BATCH), 256>>>(hid, in_ids, resp_ids, mp);
    // 9. topic softmax + gather
    topic_kernel<<<NGRP*BATCH, 256>>>(mp, tw, tb, table, ue);
    // 10. final output
    out_kernel<<<MROWS, 256>>>(X, in_ids, resp_ids, ue, out);
}

// round 3
// speedup vs baseline: 3.4607x; 1.2166x over previous
#include <cuda_runtime.h>
#include <math.h>
#include <cstdint>

// ---------------- problem constants ----------------
#define BATCH 16
#define SEQ   512
#define SIN   384
#define SRES  129
#define WID   1024
#define HEADS 16
#define DHEAD 64
#define DFF   4096
#define NTOP  50
#define NGRP  7
#define MROWS (BATCH*SEQ)   // 8192

// ---------------- scratch ----------------
__device__ float g_qkv[(size_t)MROWS * 3072];
__device__ float g_ctx[(size_t)MROWS * WID];
__device__ float g_tmp[(size_t)MROWS * DFF];
__device__ float g_y  [(size_t)MROWS * WID];
__device__ float g_hid[(size_t)MROWS * WID];
__device__ float g_mp [NGRP * BATCH * WID];
__device__ float g_ue [NGRP * BATCH * WID];

// round-to-nearest tf32 conversion (unbiased, vs RZ truncation)
__device__ __forceinline__ uint32_t f2tf(float x) {
    uint32_t r;
    asm("cvt.rna.tf32.f32 %0, %1;" : "=r"(r) : "f"(x));
    return r;
}

__device__ __forceinline__ void mma_tf32(float* c, const uint32_t* a, const uint32_t* b) {
    asm volatile(
        "mma.sync.aligned.m16n8k8.row.col.f32.tf32.tf32.f32 "
        "{%0,%1,%2,%3}, {%4,%5,%6,%7}, {%8,%9}, {%0,%1,%2,%3};"
        : "+f"(c[0]), "+f"(c[1]), "+f"(c[2]), "+f"(c[3])
        : "r"(a[0]), "r"(a[1]), "r"(a[2]), "r"(a[3]), "r"(b[0]), "r"(b[1]));
}

// ================= TF32 tensor-core GEMM =================
#define BM 128
#define BN 128
#define BK 32
#define NSTAGE 3
#define LDSW (BK + 4)
#define STAGE_F (BM * LDSW)

__device__ __forceinline__ void cpa16(float* dst, const float* src) {
    uint32_t d = (uint32_t)__cvta_generic_to_shared(dst);
    asm volatile("cp.async.cg.shared.global [%0], [%1], 16;" :: "r"(d), "l"(src));
}

__global__ __launch_bounds__(256, 2) void mma_gemm(
    const float* __restrict__ A, const float* __restrict__ Bw,
    const float* __restrict__ bias, float* __restrict__ C,
    int M, int N, int K, int dogelu)
{
    extern __shared__ float smbuf[];
    float* As = smbuf;
    float* Bs = smbuf + NSTAGE * STAGE_F;

    const int tid  = threadIdx.x;
    const int m0   = blockIdx.y * BM;
    const int n0   = blockIdx.x * BN;
    const int warp = tid >> 5, lane = tid & 31;
    const int g    = lane >> 2, tig = lane & 3;
    const int mw   = (warp >> 2) * 64;
    const int nw   = (warp & 3) * 32;

    float acc[4][4][4];
    #pragma unroll
    for (int mi = 0; mi < 4; mi++)
        #pragma unroll
        for (int ni = 0; ni < 4; ni++)
            #pragma unroll
            for (int r = 0; r < 4; r++) acc[mi][ni][r] = 0.0f;

    const int kiters = K / BK;

    #pragma unroll
    for (int s = 0; s < NSTAGE - 1; s++) {
        const int k0 = s * BK;
        #pragma unroll
        for (int i = 0; i < 4; i++) {
            int c = tid + i * 256;
            int row = c >> 3, kc = (c & 7) * 4;
            cpa16(As + s * STAGE_F + row * LDSW + kc, A  + (size_t)(m0 + row) * K + k0 + kc);
            cpa16(Bs + s * STAGE_F + row * LDSW + kc, Bw + (size_t)(n0 + row) * K + k0 + kc);
        }
        asm volatile("cp.async.commit_group;");
    }

    for (int kt = 0; kt < kiters; kt++) {
        if (kt + NSTAGE - 1 < kiters) {
            const int s = (kt + NSTAGE - 1) % NSTAGE;
            const int k0 = (kt + NSTAGE - 1) * BK;
            #pragma unroll
            for (int i = 0; i < 4; i++) {
                int c = tid + i * 256;
                int row = c >> 3, kc = (c & 7) * 4;
                cpa16(As + s * STAGE_F + row * LDSW + kc, A  + (size_t)(m0 + row) * K + k0 + kc);
                cpa16(Bs + s * STAGE_F + row * LDSW + kc, Bw + (size_t)(n0 + row) * K + k0 + kc);
            }
        }
        asm volatile("cp.async.commit_group;");
        asm volatile("cp.async.wait_group %0;" :: "n"(NSTAGE - 1));
        __syncthreads();

        const float* as = As + (kt % NSTAGE) * STAGE_F;
        const float* bs = Bs + (kt % NSTAGE) * STAGE_F;

        #pragma unroll
        for (int kk = 0; kk < BK; kk += 8) {
            uint32_t af[4][4], bf[4][2];
            #pragma unroll
            for (int mi = 0; mi < 4; mi++) {
                const float* p  = as + (mw + mi * 16 + g) * LDSW + kk + tig;
                const float* p2 = p + 8 * LDSW;
                af[mi][0] = f2tf(p[0]);
                af[mi][2] = f2tf(p[4]);
                af[mi][1] = f2tf(p2[0]);
                af[mi][3] = f2tf(p2[4]);
            }
            #pragma unroll
            for (int ni = 0; ni < 4; ni++) {
                const float* p = bs + (nw + ni * 8 + g) * LDSW + kk + tig;
                bf[ni][0] = f2tf(p[0]);
                bf[ni][1] = f2tf(p[4]);
            }
            #pragma unroll
            for (int mi = 0; mi < 4; mi++)
                #pragma unroll
                for (int ni = 0; ni < 4; ni++)
                    mma_tf32(acc[mi][ni], af[mi], bf[ni]);
        }
        __syncthreads();
    }

    #pragma unroll
    for (int ni = 0; ni < 4; ni++) {
        const int cc = n0 + nw + ni * 8 + 2 * tig;
        const float bv0 = bias[cc], bv1 = bias[cc + 1];
        #pragma unroll
        for (int mi = 0; mi < 4; mi++) {
            const int r0 = m0 + mw + mi * 16 + g;
            float v00 = acc[mi][ni][0] + bv0;
            float v01 = acc[mi][ni][1] + bv1;
            float v10 = acc[mi][ni][2] + bv0;
            float v11 = acc[mi][ni][3] + bv1;
            if (dogelu) {
                v00 = 0.5f * v00 * (1.0f + erff(v00 * 0.70710678118654752f));
                v01 = 0.5f * v01 * (1.0f + erff(v01 * 0.70710678118654752f));
                v10 = 0.5f * v10 * (1.0f + erff(v10 * 0.70710678118654752f));
                v11 = 0.5f * v11 * (1.0f + erff(v11 * 0.70710678118654752f));
            }
            *(float2*)(C + (size_t)r0 * N + cc)       = make_float2(v00, v01);
            *(float2*)(C + (size_t)(r0 + 8) * N + cc) = make_float2(v10, v11);
        }
    }
}

// ================= tensor-core flash attention =================
// block = (q-tile of 128, b*h). 8 warps; warp owns 16 q rows.
// S = Q@K^T (tf32 mma) -> register softmax (quad shuffles) -> P via smem -> P@V (tf32 mma).
#define AP 68   // smem row pitch (64 + 4): conflict-free for 4g+t access

__global__ __launch_bounds__(256, 2) void attn_mma_kernel(
    const float* __restrict__ qkv, float* __restrict__ ctx)
{
    __shared__ float Qs[128][AP];
    __shared__ float Ks[64][AP];
    __shared__ float Vs[64][AP];
    __shared__ float Ps[128][AP];

    const int bh = blockIdx.y;
    const int b = bh >> 4, h = bh & 15;
    const int q0 = blockIdx.x * 128;
    const int tid = threadIdx.x;
    const int warp = tid >> 5, lane = tid & 31;
    const int g = lane >> 2, t = lane & 3;
    const int mw = warp * 16;

    // stage Q (pre-scaled by 1/8)
    #pragma unroll
    for (int i = 0; i < 8; i++) {
        int idx = tid + i * 256;
        int row = idx >> 4, c4 = (idx & 15) * 4;
        float4 v = *(const float4*)(qkv + (size_t)(b*SEQ + q0 + row) * 3072 + h*DHEAD + c4);
        v.x *= 0.125f; v.y *= 0.125f; v.z *= 0.125f; v.w *= 0.125f;
        *(float4*)&Qs[row][c4] = v;
    }

    float o[8][4];
    #pragma unroll
    for (int nt = 0; nt < 8; nt++)
        #pragma unroll
        for (int r = 0; r < 4; r++) o[nt][r] = 0.0f;
    float m0 = -1e30f, m1 = -1e30f, l0 = 0.0f, l1 = 0.0f;

    for (int kb = 0; kb < SEQ; kb += 64) {
        // stage K, V block (64 x 64)
        __syncthreads();
        #pragma unroll
        for (int i = 0; i < 4; i++) {
            int idx = tid + i * 256;
            int row = idx >> 4, c4 = (idx & 15) * 4;
            const float* base = qkv + (size_t)(b*SEQ + kb + row) * 3072 + h*DHEAD + c4;
            *(float4*)&Ks[row][c4] = *(const float4*)(base + 1024);
            *(float4*)&Vs[row][c4] = *(const float4*)(base + 2048);
        }
        __syncthreads();

        // ---- S = Q @ K^T ----
        float sacc[8][4];
        #pragma unroll
        for (int nt = 0; nt < 8; nt++)
            #pragma unroll
            for (int r = 0; r < 4; r++) sacc[nt][r] = 0.0f;

        #pragma unroll
        for (int kt = 0; kt < 8; kt++) {
            uint32_t af[4];
            const float* p  = &Qs[mw + g][kt*8 + t];
            const float* p2 = p + 8 * AP;
            af[0] = f2tf(p[0]);  af[2] = f2tf(p[4]);
            af[1] = f2tf(p2[0]); af[3] = f2tf(p2[4]);
            #pragma unroll
            for (int nt = 0; nt < 8; nt++) {
                uint32_t bf[2];
                const float* pb = &Ks[nt*8 + g][kt*8 + t];
                bf[0] = f2tf(pb[0]); bf[1] = f2tf(pb[4]);
                mma_tf32(sacc[nt], af, bf);
            }
        }

        // ---- online softmax (rows g and g+8, stats replicated in quad) ----
        float rmax0 = -1e30f, rmax1 = -1e30f;
        #pragma unroll
        for (int nt = 0; nt < 8; nt++) {
            rmax0 = fmaxf(rmax0, fmaxf(sacc[nt][0], sacc[nt][1]));
            rmax1 = fmaxf(rmax1, fmaxf(sacc[nt][2], sacc[nt][3]));
        }
        #pragma unroll
        for (int d = 1; d < 4; d <<= 1) {
            rmax0 = fmaxf(rmax0, __shfl_xor_sync(0xffffffffu, rmax0, d));
            rmax1 = fmaxf(rmax1, __shfl_xor_sync(0xffffffffu, rmax1, d));
        }
        float m0n = fmaxf(m0, rmax0), m1n = fmaxf(m1, rmax1);
        float c0 = __expf(m0 - m0n), c1 = __expf(m1 - m1n);
        m0 = m0n; m1 = m1n;

        float sum0 = 0.0f, sum1 = 0.0f;
        #pragma unroll
        for (int nt = 0; nt < 8; nt++) {
            sacc[nt][0] = __expf(sacc[nt][0] - m0);
            sacc[nt][1] = __expf(sacc[nt][1] - m0);
            sacc[nt][2] = __expf(sacc[nt][2] - m1);
            sacc[nt][3] = __expf(sacc[nt][3] - m1);
            sum0 += sacc[nt][0] + sacc[nt][1];
            sum1 += sacc[nt][2] + sacc[nt][3];
        }
        #pragma unroll
        for (int d = 1; d < 4; d <<= 1) {
            sum0 += __shfl_xor_sync(0xffffffffu, sum0, d);
            sum1 += __shfl_xor_sync(0xffffffffu, sum1, d);
        }
        l0 = l0 * c0 + sum0;
        l1 = l1 * c1 + sum1;
        #pragma unroll
        for (int nt = 0; nt < 8; nt++) {
            o[nt][0] *= c0; o[nt][1] *= c0;
            o[nt][2] *= c1; o[nt][3] *= c1;
        }

        // write P to smem (relayout acc-frag -> a-frag via smem)
        #pragma unroll
        for (int nt = 0; nt < 8; nt++) {
            *(float2*)&Ps[mw + g][nt*8 + 2*t]     = make_float2(sacc[nt][0], sacc[nt][1]);
            *(float2*)&Ps[mw + g + 8][nt*8 + 2*t] = make_float2(sacc[nt][2], sacc[nt][3]);
        }
        __syncwarp();

        // ---- O += P @ V ----
        #pragma unroll
        for (int kt = 0; kt < 8; kt++) {
            uint32_t af[4];
            const float* p  = &Ps[mw + g][kt*8 + t];
            const float* p2 = p + 8 * AP;
            af[0] = f2tf(p[0]);  af[2] = f2tf(p[4]);
            af[1] = f2tf(p2[0]); af[3] = f2tf(p2[4]);
            #pragma unroll
            for (int nt = 0; nt < 8; nt++) {
                uint32_t bf[2];
                bf[0] = f2tf(Vs[kt*8 + t][nt*8 + g]);
                bf[1] = f2tf(Vs[kt*8 + t + 4][nt*8 + g]);
                mma_tf32(o[nt], af, bf);
            }
        }
    }

    float inv0 = 1.0f / l0, inv1 = 1.0f / l1;
    const int r0 = b*SEQ + q0 + mw + g;
    const int cbase = h*DHEAD + 2*t;
    #pragma unroll
    for (int nt = 0; nt < 8; nt++) {
        *(float2*)(ctx + (size_t)r0 * WID + cbase + nt*8) =
            make_float2(o[nt][0]*inv0, o[nt][1]*inv0);
        *(float2*)(ctx + (size_t)(r0 + 8) * WID + cbase + nt*8) =
            make_float2(o[nt][2]*inv1, o[nt][3]*inv1);
    }
}

// ---------------- residual add + LayerNorm ----------------
__global__ __launch_bounds__(256) void add_ln_kernel(
    const float* __restrict__ resid, const float* __restrict__ x,
    const float* __restrict__ gg, const float* __restrict__ bb,
    float* __restrict__ out)
{
    __shared__ float2 sm[8];
    const size_t row = blockIdx.x;
    const int tid = threadIdx.x;

    float4 r = *(const float4*)(resid + row*WID + tid*4);
    float4 v = *(const float4*)(x     + row*WID + tid*4);
    float4 tv;
    tv.x = r.x + v.x; tv.y = r.y + v.y; tv.z = r.z + v.z; tv.w = r.w + v.w;

    float s = tv.x + tv.y + tv.z + tv.w;
    float qq = tv.x*tv.x + tv.y*tv.y + tv.z*tv.z + tv.w*tv.w;

    int lane = tid & 31, warp = tid >> 5;
    #pragma unroll
    for (int o = 16; o > 0; o >>= 1) {
        s  += __shfl_down_sync(0xffffffffu, s,  o);
        qq += __shfl_down_sync(0xffffffffu, qq, o);
    }
    if (lane == 0) sm[warp] = make_float2(s, qq);
    __syncthreads();
    if (warp == 0) {
        float2 w2 = (lane < 8) ? sm[lane] : make_float2(0.f, 0.f);
        #pragma unroll
        for (int o = 4; o > 0; o >>= 1) {
            w2.x += __shfl_down_sync(0xffffffffu, w2.x, o);
            w2.y += __shfl_down_sync(0xffffffffu, w2.y, o);
        }
        if (lane == 0) sm[0] = w2;
    }
    __syncthreads();
    float mean = sm[0].x * (1.0f/WID);
    float var  = sm[0].y * (1.0f/WID) - mean*mean;
    float rstd = rsqrtf(var + 1e-5f);

    float4 g4 = *(const float4*)(gg + tid*4);
    float4 b4 = *(const float4*)(bb + tid*4);
    float4 o;
    o.x = (tv.x - mean)*rstd*g4.x + b4.x;
    o.y = (tv.y - mean)*rstd*g4.y + b4.y;
    o.z = (tv.z - mean)*rstd*g4.z + b4.z;
    o.w = (tv.w - mean)*rstd*g4.w + b4.w;
    *(float4*)(out + row*WID + tid*4) = o;
}

// ---------------- masked max-pool ----------------
__global__ __launch_bounds__(256) void maxpool_kernel(
    const float* __restrict__ hidden, const int* __restrict__ in_ids,
    const int* __restrict__ resp_ids, float* __restrict__ mp)
{
    const int g = blockIdx.x;
    const int b = blockIdx.y;
    const int tid = threadIdx.x;
    __shared__ unsigned char flag[SEQ];

    for (int s = tid; s < SEQ; s += 256) {
        bool f = false;
        if (g < 6) { if (s < SIN) f = (in_ids[b*SIN + s] == g + 1); }
        else       { if (s >= SIN) f = (resp_ids[b*SRES + (s - SIN + 1)] == 1); }
        flag[s] = f ? 1 : 0;
    }
    __syncthreads();

    const int w = tid * 4;
    float4 vm = make_float4(0.f, 0.f, 0.f, 0.f);
    for (int s = 0; s < SEQ; s++) {
        if (flag[s]) {
            float4 hv = *(const float4*)(hidden + (size_t)(b*SEQ + s)*WID + w);
            vm.x = fmaxf(vm.x, hv.x); vm.y = fmaxf(vm.y, hv.y);
            vm.z = fmaxf(vm.z, hv.z); vm.w = fmaxf(vm.w, hv.w);
        }
    }
    *(float4*)(mp + (size_t)(g*BATCH + b)*WID + w) = vm;
}

// ---------------- topic softmax + gather ----------------
__global__ __launch_bounds__(256) void topic_kernel(
    const float* __restrict__ mp, const float* __restrict__ tw,
    const float* __restrict__ tb, const float* __restrict__ table,
    float* __restrict__ ue)
{
    const int gb = blockIdx.x;
    const int tid = threadIdx.x;
    __shared__ float mpv[WID];
    __shared__ float probs[NTOP];
    __shared__ float logits[NTOP];

    *(float4*)&mpv[tid*4] = *(const float4*)(mp + (size_t)gb*WID + tid*4);
    __syncthreads();

    const int warp = tid >> 5, lane = tid & 31;
    for (int t = warp; t < NTOP; t += 8) {
        const float* wr = tw + (size_t)t * WID;
        float s = 0.0f;
        for (int w = lane; w < WID; w += 32) s = fmaf(mpv[w], wr[w], s);
        #pragma unroll
        for (int o = 16; o > 0; o >>= 1) s += __shfl_down_sync(0xffffffffu, s, o);
        if (lane == 0) logits[t] = s + tb[t];
    }
    __syncthreads();

    if (tid == 0) {
        float m = -1e30f;
        for (int t = 0; t < NTOP; t++) m = fmaxf(m, logits[t]);
        float sum = 0.0f;
        for (int t = 0; t < NTOP; t++) { float e = expf(logits[t] - m); probs[t] = e; sum += e; }
        float inv = 1.0f / sum;
        for (int t = 0; t < NTOP; t++) probs[t] *= inv;
    }
    __syncthreads();

    const int w = tid * 4;
    float4 a = make_float4(0.f, 0.f, 0.f, 0.f);
    for (int t = 0; t < NTOP; t++) {
        float p = probs[t];
        float4 tv = *(const float4*)(table + (size_t)t*WID + w);
        a.x = fmaf(p, tv.x, a.x); a.y = fmaf(p, tv.y, a.y);
        a.z = fmaf(p, tv.z, a.z); a.w = fmaf(p, tv.w, a.w);
    }
    *(float4*)(ue + (size_t)gb*WID + w) = a;
}

// ---------------- final output ----------------
__global__ __launch_bounds__(256) void out_kernel(
    const float* __restrict__ X, const int* __restrict__ in_ids,
    const int* __restrict__ resp_ids, const float* __restrict__ ue,
    float* __restrict__ out)
{
    const int bs = blockIdx.x;
    const int b = bs >> 9, s = bs & 511;
    int g = -1; float c = 0.0f;
    if (s < SIN) {
        int v = in_ids[b*SIN + s];
        if (v > 0)      { g = v - 1;   c = 1.0f; }
        else if (v < 0) { g = -v - 1;  c = 2.0f; }
    } else {
        int v = resp_ids[b*SRES + (s - SIN + 1)];
        if (v == 1)       { g = 6; c = 1.0f; }
        else if (v == -1) { g = 6; c = 2.0f; }
    }
    const int w = threadIdx.x * 4;
    float4 xv = *(const float4*)(X + (size_t)bs*WID + w);
    if (g >= 0) {
        float4 u = *(const float4*)(ue + (size_t)(g*BATCH + b)*WID + w);
        xv.x = fmaf(c, u.x, xv.x); xv.y = fmaf(c, u.y, xv.y);
        xv.z = fmaf(c, u.z, xv.z); xv.w = fmaf(c, u.w, xv.w);
    }
    *(float4*)(out + (size_t)bs*WID + w) = xv;
}

// ---------------- launch ----------------
extern "C" void kernel_launch(void* const* d_in, const int* in_sizes, int n_in,
                              void* d_out, int out_size)
{
    const float* X       = (const float*)d_in[0];
    const int*   in_ids  = (const int*)  d_in[1];
    const int*   resp_ids= (const int*)  d_in[2];
    const float* Wqkv    = (const float*)d_in[3];
    const float* bqkv    = (const float*)d_in[4];
    const float* Wo      = (const float*)d_in[5];
    const float* bo      = (const float*)d_in[6];
    const float* ln1g    = (const float*)d_in[7];
    const float* ln1b    = (const float*)d_in[8];
    const float* W1      = (const float*)d_in[9];
    const float* b1      = (const float*)d_in[10];
    const float* W2      = (const float*)d_in[11];
    const float* b2      = (const float*)d_in[12];
    const float* ln2g    = (const float*)d_in[13];
    const float* ln2b    = (const float*)d_in[14];
    const float* tw      = (const float*)d_in[15];
    const float* tb      = (const float*)d_in[16];
    const float* table   = (const float*)d_in[17];
    float* out = (float*)d_out;

    float *qkv, *ctx, *tmp, *y, *hid, *mp, *ue;
    cudaGetSymbolAddress((void**)&qkv, g_qkv);
    cudaGetSymbolAddress((void**)&ctx, g_ctx);
    cudaGetSymbolAddress((void**)&tmp, g_tmp);
    cudaGetSymbolAddress((void**)&y,   g_y);
    cudaGetSymbolAddress((void**)&hid, g_hid);
    cudaGetSymbolAddress((void**)&mp,  g_mp);
    cudaGetSymbolAddress((void**)&ue,  g_ue);

    const int smem = NSTAGE * STAGE_F * 2 * sizeof(float);
    cudaFuncSetAttribute(mma_gemm, cudaFuncAttributeMaxDynamicSharedMemorySize, smem);

    mma_gemm<<<dim3(3072/BN, MROWS/BM), 256, smem>>>(X, Wqkv, bqkv, qkv, MROWS, 3072, 1024, 0);
    attn_mma_kernel<<<dim3(SEQ/128, BATCH*HEADS), 256>>>(qkv, ctx);
    mma_gemm<<<dim3(WID/BN, MROWS/BM), 256, smem>>>(ctx, Wo, bo, tmp, MROWS, WID, 1024, 0);
    add_ln_kernel<<<MROWS, 256>>>(X, tmp, ln1g, ln1b, y);
    mma_gemm<<<dim3(DFF/BN, MROWS/BM), 256, smem>>>(y, W1, b1, tmp, MROWS, DFF, 1024, 1);
    mma_gemm<<<dim3(WID/BN, MROWS/BM), 256, smem>>>(tmp, W2, b2, ctx, MROWS, WID, 4096, 0);
    add_ln_kernel<<<MROWS, 256>>>(y, ctx, ln2g, ln2b, hid);
    maxpool_kernel<<<dim3(NGRP, BATCH), 256>>>(hid, in_ids, resp_ids, mp);
    topic_kernel<<<NGRP*BATCH, 256>>>(mp, tw, tb, table, ue);
    out_kernel<<<MROWS, 256>>>(X, in_ids, resp_ids, ue, out);
}

// round 7
// speedup vs baseline: 3.5548x; 1.0272x over previous
#include <cuda_runtime.h>
#include <math.h>
#include <cstdint>

// ---------------- problem constants ----------------
#define BATCH 16
#define SEQ   512
#define SIN   384
#define SRES  129
#define WID   1024
#define HEADS 16
#define DHEAD 64
#define DFF   4096
#define NTOP  50
#define NGRP  7
#define MROWS (BATCH*SEQ)   // 8192

// ---------------- scratch ----------------
__device__ float g_qkv[(size_t)MROWS * 3072];
__device__ float g_ctx[(size_t)MROWS * WID];
__device__ float g_tmp[(size_t)MROWS * DFF];
__device__ float g_y  [(size_t)MROWS * WID];
__device__ float g_hid[(size_t)MROWS * WID];      // also holds rounded X early on
__device__ float g_wr [12582912];                  // rounded weights (48 MB)
__device__ float g_mp [NGRP * BATCH * WID];
__device__ float g_ue [NGRP * BATCH * WID];

// round-to-nearest tf32
__device__ __forceinline__ uint32_t f2tf(float x) {
    uint32_t r;
    asm("cvt.rna.tf32.f32 %0, %1;" : "=r"(r) : "f"(x));
    return r;
}
__device__ __forceinline__ float rtf(float x) { return __uint_as_float(f2tf(x)); }

__device__ __forceinline__ void mma_tf32(float* c, const uint32_t* a, const uint32_t* b) {
    asm volatile(
        "mma.sync.aligned.m16n8k8.row.col.f32.tf32.tf32.f32 "
        "{%0,%1,%2,%3}, {%4,%5,%6,%7}, {%8,%9}, {%0,%1,%2,%3};"
        : "+f"(c[0]), "+f"(c[1]), "+f"(c[2]), "+f"(c[3])
        : "r"(a[0]), "r"(a[1]), "r"(a[2]), "r"(a[3]), "r"(b[0]), "r"(b[1]));
}

// ---------------- fused multi-tensor tf32 pre-round ----------------
__global__ __launch_bounds__(256) void round_multi(
    const float* s0, float* d0, int n0,
    const float* s1, float* d1, int n1,
    const float* s2, float* d2, int n2,
    const float* s3, float* d3, int n3,
    const float* s4, float* d4, int n4)   // counts in float4 units
{
    int total = n0 + n1 + n2 + n3 + n4;
    for (int idx = blockIdx.x * 256 + threadIdx.x; idx < total; idx += gridDim.x * 256) {
        int i = idx;
        const float* s; float* d;
        if (i < n0) { s = s0; d = d0; }
        else { i -= n0;
            if (i < n1) { s = s1; d = d1; }
            else { i -= n1;
                if (i < n2) { s = s2; d = d2; }
                else { i -= n2;
                    if (i < n3) { s = s3; d = d3; }
                    else { i -= n3; s = s4; d = d4; } } } }
        float4 v = *(const float4*)(s + (size_t)i * 4);
        v.x = rtf(v.x); v.y = rtf(v.y); v.z = rtf(v.z); v.w = rtf(v.w);
        *(float4*)(d + (size_t)i * 4) = v;
    }
}

// ================= TF32 tensor-core GEMM (pre-rounded operands) =================
// mode: bit0 = exact GELU, bit1 = round output to tf32
#define BM 128
#define BN 128
#define BK 32
#define NSTAGE 3
#define LDSW (BK + 4)
#define STAGE_F (BM * LDSW)

__device__ __forceinline__ void cpa16(float* dst, const float* src) {
    uint32_t d = (uint32_t)__cvta_generic_to_shared(dst);
    asm volatile("cp.async.cg.shared.global [%0], [%1], 16;" :: "r"(d), "l"(src));
}

__global__ __launch_bounds__(256, 2) void mma_gemm(
    const float* __restrict__ A, const float* __restrict__ Bw,
    const float* __restrict__ bias, float* __restrict__ C,
    int M, int N, int K, int mode)
{
    extern __shared__ float smbuf[];
    float* As = smbuf;
    float* Bs = smbuf + NSTAGE * STAGE_F;

    const int tid  = threadIdx.x;
    const int m0   = blockIdx.y * BM;
    const int n0   = blockIdx.x * BN;
    const int warp = tid >> 5, lane = tid & 31;
    const int g    = lane >> 2, tig = lane & 3;
    const int mw   = (warp >> 2) * 64;
    const int nw   = (warp & 3) * 32;

    float acc[4][4][4];
    #pragma unroll
    for (int mi = 0; mi < 4; mi++)
        #pragma unroll
        for (int ni = 0; ni < 4; ni++)
            #pragma unroll
            for (int r = 0; r < 4; r++) acc[mi][ni][r] = 0.0f;

    const int kiters = K / BK;

    #pragma unroll
    for (int s = 0; s < NSTAGE - 1; s++) {
        const int k0 = s * BK;
        #pragma unroll
        for (int i = 0; i < 4; i++) {
            int c = tid + i * 256;
            int row = c >> 3, kc = (c & 7) * 4;
            cpa16(As + s * STAGE_F + row * LDSW + kc, A  + (size_t)(m0 + row) * K + k0 + kc);
            cpa16(Bs + s * STAGE_F + row * LDSW + kc, Bw + (size_t)(n0 + row) * K + k0 + kc);
        }
        asm volatile("cp.async.commit_group;");
    }

    for (int kt = 0; kt < kiters; kt++) {
        if (kt + NSTAGE - 1 < kiters) {
            const int s = (kt + NSTAGE - 1) % NSTAGE;
            const int k0 = (kt + NSTAGE - 1) * BK;
            #pragma unroll
            for (int i = 0; i < 4; i++) {
                int c = tid + i * 256;
                int row = c >> 3, kc = (c & 7) * 4;
                cpa16(As + s * STAGE_F + row * LDSW + kc, A  + (size_t)(m0 + row) * K + k0 + kc);
                cpa16(Bs + s * STAGE_F + row * LDSW + kc, Bw + (size_t)(n0 + row) * K + k0 + kc);
            }
        }
        asm volatile("cp.async.commit_group;");
        asm volatile("cp.async.wait_group %0;" :: "n"(NSTAGE - 1));
        __syncthreads();

        const float* as = As + (kt % NSTAGE) * STAGE_F;
        const float* bs = Bs + (kt % NSTAGE) * STAGE_F;

        #pragma unroll
        for (int kk = 0; kk < BK; kk += 8) {
            uint32_t af[4][4], bf[4][2];
            #pragma unroll
            for (int mi = 0; mi < 4; mi++) {
                const float* p  = as + (mw + mi * 16 + g) * LDSW + kk + tig;
                const float* p2 = p + 8 * LDSW;
                af[mi][0] = __float_as_uint(p[0]);
                af[mi][2] = __float_as_uint(p[4]);
                af[mi][1] = __float_as_uint(p2[0]);
                af[mi][3] = __float_as_uint(p2[4]);
            }
            #pragma unroll
            for (int ni = 0; ni < 4; ni++) {
                const float* p = bs + (nw + ni * 8 + g) * LDSW + kk + tig;
                bf[ni][0] = __float_as_uint(p[0]);
                bf[ni][1] = __float_as_uint(p[4]);
            }
            #pragma unroll
            for (int mi = 0; mi < 4; mi++)
                #pragma unroll
                for (int ni = 0; ni < 4; ni++)
                    mma_tf32(acc[mi][ni], af[mi], bf[ni]);
        }
        __syncthreads();
    }

    const bool dogelu  = (mode & 1) != 0;
    const bool doround = (mode & 2) != 0;
    #pragma unroll
    for (int ni = 0; ni < 4; ni++) {
        const int cc = n0 + nw + ni * 8 + 2 * tig;
        const float bv0 = bias[cc], bv1 = bias[cc + 1];
        #pragma unroll
        for (int mi = 0; mi < 4; mi++) {
            const int r0 = m0 + mw + mi * 16 + g;
            float v00 = acc[mi][ni][0] + bv0;
            float v01 = acc[mi][ni][1] + bv1;
            float v10 = acc[mi][ni][2] + bv0;
            float v11 = acc[mi][ni][3] + bv1;
            if (dogelu) {
                v00 = 0.5f * v00 * (1.0f + erff(v00 * 0.70710678118654752f));
                v01 = 0.5f * v01 * (1.0f + erff(v01 * 0.70710678118654752f));
                v10 = 0.5f * v10 * (1.0f + erff(v10 * 0.70710678118654752f));
                v11 = 0.5f * v11 * (1.0f + erff(v11 * 0.70710678118654752f));
            }
            if (doround) {
                v00 = rtf(v00); v01 = rtf(v01); v10 = rtf(v10); v11 = rtf(v11);
            }
            *(float2*)(C + (size_t)r0 * N + cc)       = make_float2(v00, v01);
            *(float2*)(C + (size_t)(r0 + 8) * N + cc) = make_float2(v10, v11);
        }
    }
}

// ================= tensor-core flash attention (qkv pre-rounded to tf32) =================
#define AP 68

__global__ __launch_bounds__(256, 2) void attn_mma_kernel(
    const float* __restrict__ qkv, float* __restrict__ ctx)
{
    __shared__ float Qs[128][AP];
    __shared__ float Ks[64][AP];
    __shared__ float Vs[64][AP];
    __shared__ float Ps[128][AP];

    const int bh = blockIdx.y;
    const int b = bh >> 4, h = bh & 15;
    const int q0 = blockIdx.x * 128;
    const int tid = threadIdx.x;
    const int warp = tid >> 5, lane = tid & 31;
    const int g = lane >> 2, t = lane & 3;
    const int mw = warp * 16;

    // stage Q (pre-scaled by 1/8; power-of-2 scale preserves tf32-exactness)
    #pragma unroll
    for (int i = 0; i < 8; i++) {
        int idx = tid + i * 256;
        int row = idx >> 4, c4 = (idx & 15) * 4;
        float4 v = *(const float4*)(qkv + (size_t)(b*SEQ + q0 + row) * 3072 + h*DHEAD + c4);
        v.x *= 0.125f; v.y *= 0.125f; v.z *= 0.125f; v.w *= 0.125f;
        *(float4*)&Qs[row][c4] = v;
    }

    float o[8][4];
    #pragma unroll
    for (int nt = 0; nt < 8; nt++)
        #pragma unroll
        for (int r = 0; r < 4; r++) o[nt][r] = 0.0f;
    float m0 = -1e30f, m1 = -1e30f, l0 = 0.0f, l1 = 0.0f;

    for (int kb = 0; kb < SEQ; kb += 64) {
        __syncthreads();
        #pragma unroll
        for (int i = 0; i < 4; i++) {
            int idx = tid + i * 256;
            int row = idx >> 4, c4 = (idx & 15) * 4;
            const float* base = qkv + (size_t)(b*SEQ + kb + row) * 3072 + h*DHEAD + c4;
            *(float4*)&Ks[row][c4] = *(const float4*)(base + 1024);
            *(float4*)&Vs[row][c4] = *(const float4*)(base + 2048);
        }
        __syncthreads();

        // ---- S = Q @ K^T ----
        float sacc[8][4];
        #pragma unroll
        for (int nt = 0; nt < 8; nt++)
            #pragma unroll
            for (int r = 0; r < 4; r++) sacc[nt][r] = 0.0f;

        #pragma unroll
        for (int kt = 0; kt < 8; kt++) {
            uint32_t af[4];
            const float* p  = &Qs[mw + g][kt*8 + t];
            const float* p2 = p + 8 * AP;
            af[0] = __float_as_uint(p[0]);  af[2] = __float_as_uint(p[4]);
            af[1] = __float_as_uint(p2[0]); af[3] = __float_as_uint(p2[4]);
            #pragma unroll
            for (int nt = 0; nt < 8; nt++) {
                uint32_t bf[2];
                const float* pb = &Ks[nt*8 + g][kt*8 + t];
                bf[0] = __float_as_uint(pb[0]); bf[1] = __float_as_uint(pb[4]);
                mma_tf32(sacc[nt], af, bf);
            }
        }

        // ---- online softmax ----
        float rmax0 = -1e30f, rmax1 = -1e30f;
        #pragma unroll
        for (int nt = 0; nt < 8; nt++) {
            rmax0 = fmaxf(rmax0, fmaxf(sacc[nt][0], sacc[nt][1]));
            rmax1 = fmaxf(rmax1, fmaxf(sacc[nt][2], sacc[nt][3]));
        }
        #pragma unroll
        for (int d = 1; d < 4; d <<= 1) {
            rmax0 = fmaxf(rmax0, __shfl_xor_sync(0xffffffffu, rmax0, d));
            rmax1 = fmaxf(rmax1, __shfl_xor_sync(0xffffffffu, rmax1, d));
        }
        float m0n = fmaxf(m0, rmax0), m1n = fmaxf(m1, rmax1);
        float c0 = __expf(m0 - m0n), c1 = __expf(m1 - m1n);
        m0 = m0n; m1 = m1n;

        float sum0 = 0.0f, sum1 = 0.0f;
        #pragma unroll
        for (int nt = 0; nt < 8; nt++) {
            sacc[nt][0] = __expf(sacc[nt][0] - m0);
            sacc[nt][1] = __expf(sacc[nt][1] - m0);
            sacc[nt][2] = __expf(sacc[nt][2] - m1);
            sacc[nt][3] = __expf(sacc[nt][3] - m1);
            sum0 += sacc[nt][0] + sacc[nt][1];
            sum1 += sacc[nt][2] + sacc[nt][3];
        }
        #pragma unroll
        for (int d = 1; d < 4; d <<= 1) {
            sum0 += __shfl_xor_sync(0xffffffffu, sum0, d);
            sum1 += __shfl_xor_sync(0xffffffffu, sum1, d);
        }
        l0 = l0 * c0 + sum0;
        l1 = l1 * c1 + sum1;
        #pragma unroll
        for (int nt = 0; nt < 8; nt++) {
            o[nt][0] *= c0; o[nt][1] *= c0;
            o[nt][2] *= c1; o[nt][3] *= c1;
        }

        // write P (rounded once here; consumed as raw tf32 bits below)
        #pragma unroll
        for (int nt = 0; nt < 8; nt++) {
            *(float2*)&Ps[mw + g][nt*8 + 2*t]     = make_float2(rtf(sacc[nt][0]), rtf(sacc[nt][1]));
            *(float2*)&Ps[mw + g + 8][nt*8 + 2*t] = make_float2(rtf(sacc[nt][2]), rtf(sacc[nt][3]));
        }
        __syncwarp();

        // ---- O += P @ V ----
        #pragma unroll
        for (int kt = 0; kt < 8; kt++) {
            uint32_t af[4];
            const float* p  = &Ps[mw + g][kt*8 + t];
            const float* p2 = p + 8 * AP;
            af[0] = __float_as_uint(p[0]);  af[2] = __float_as_uint(p[4]);
            af[1] = __float_as_uint(p2[0]); af[3] = __float_as_uint(p2[4]);
            #pragma unroll
            for (int nt = 0; nt < 8; nt++) {
                uint32_t bf[2];
                bf[0] = __float_as_uint(Vs[kt*8 + t][nt*8 + g]);
                bf[1] = __float_as_uint(Vs[kt*8 + t + 4][nt*8 + g]);
                mma_tf32(o[nt], af, bf);
            }
        }
    }

    // output rounded to tf32 (feeds proj GEMM A operand)
    float inv0 = 1.0f / l0, inv1 = 1.0f / l1;
    const int r0 = b*SEQ + q0 + mw + g;
    const int cbase = h*DHEAD + 2*t;
    #pragma unroll
    for (int nt = 0; nt < 8; nt++) {
        *(float2*)(ctx + (size_t)r0 * WID + cbase + nt*8) =
            make_float2(rtf(o[nt][0]*inv0), rtf(o[nt][1]*inv0));
        *(float2*)(ctx + (size_t)(r0 + 8) * WID + cbase + nt*8) =
            make_float2(rtf(o[nt][2]*inv1), rtf(o[nt][3]*inv1));
    }
}

// ---------------- residual add + LayerNorm (+ optional rounded copy) ----------------
__global__ __launch_bounds__(256) void add_ln_kernel(
    const float* __restrict__ resid, const float* __restrict__ x,
    const float* __restrict__ gg, const float* __restrict__ bb,
    float* __restrict__ out, float* __restrict__ outr)
{
    __shared__ float2 sm[8];
    const size_t row = blockIdx.x;
    const int tid = threadIdx.x;

    float4 r = *(const float4*)(resid + row*WID + tid*4);
    float4 v = *(const float4*)(x     + row*WID + tid*4);
    float4 tv;
    tv.x = r.x + v.x; tv.y = r.y + v.y; tv.z = r.z + v.z; tv.w = r.w + v.w;

    float s = tv.x + tv.y + tv.z + tv.w;
    float qq = tv.x*tv.x + tv.y*tv.y + tv.z*tv.z + tv.w*tv.w;

    int lane = tid & 31, warp = tid >> 5;
    #pragma unroll
    for (int o = 16; o > 0; o >>= 1) {
        s  += __shfl_down_sync(0xffffffffu, s,  o);
        qq += __shfl_down_sync(0xffffffffu, qq, o);
    }
    if (lane == 0) sm[warp] = make_float2(s, qq);
    __syncthreads();
    if (warp == 0) {
        float2 w2 = (lane < 8) ? sm[lane] : make_float2(0.f, 0.f);
        #pragma unroll
        for (int o = 4; o > 0; o >>= 1) {
            w2.x += __shfl_down_sync(0xffffffffu, w2.x, o);
            w2.y += __shfl_down_sync(0xffffffffu, w2.y, o);
        }
        if (lane == 0) sm[0] = w2;
    }
    __syncthreads();
    float mean = sm[0].x * (1.0f/WID);
    float var  = sm[0].y * (1.0f/WID) - mean*mean;
    float rstd = rsqrtf(var + 1e-5f);

    float4 g4 = *(const float4*)(gg + tid*4);
    float4 b4 = *(const float4*)(bb + tid*4);
    float4 o;
    o.x = (tv.x - mean)*rstd*g4.x + b4.x;
    o.y = (tv.y - mean)*rstd*g4.y + b4.y;
    o.z = (tv.z - mean)*rstd*g4.z + b4.z;
    o.w = (tv.w - mean)*rstd*g4.w + b4.w;
    *(float4*)(out + row*WID + tid*4) = o;
    if (outr) {
        float4 orr;
        orr.x = rtf(o.x); orr.y = rtf(o.y); orr.z = rtf(o.z); orr.w = rtf(o.w);
        *(float4*)(outr + row*WID + tid*4) = orr;
    }
}

// ---------------- masked max-pool ----------------
__global__ __launch_bounds__(256) void maxpool_kernel(
    const float* __restrict__ hidden, const int* __restrict__ in_ids,
    const int* __restrict__ resp_ids, float* __restrict__ mp)
{
    const int g = blockIdx.x;
    const int b = blockIdx.y;
    const int tid = threadIdx.x;
    __shared__ unsigned char flag[SEQ];

    for (int s = tid; s < SEQ; s += 256) {
        bool f = false;
        if (g < 6) { if (s < SIN) f = (in_ids[b*SIN + s] == g + 1); }
        else       { if (s >= SIN) f = (resp_ids[b*SRES + (s - SIN + 1)] == 1); }
        flag[s] = f ? 1 : 0;
    }
    __syncthreads();

    const int w = tid * 4;
    float4 vm = make_float4(0.f, 0.f, 0.f, 0.f);
    for (int s = 0; s < SEQ; s++) {
        if (flag[s]) {
            float4 hv = *(const float4*)(hidden + (size_t)(b*SEQ + s)*WID + w);
            vm.x = fmaxf(vm.x, hv.x); vm.y = fmaxf(vm.y, hv.y);
            vm.z = fmaxf(vm.z, hv.z); vm.w = fmaxf(vm.w, hv.w);
        }
    }
    *(float4*)(mp + (size_t)(g*BATCH + b)*WID + w) = vm;
}

// ---------------- topic softmax + gather ----------------
__global__ __launch_bounds__(256) void topic_kernel(
    const float* __restrict__ mp, const float* __restrict__ tw,
    const float* __restrict__ tb, const float* __restrict__ table,
    float* __restrict__ ue)
{
    const int gb = blockIdx.x;
    const int tid = threadIdx.x;
    __shared__ float mpv[WID];
    __shared__ float probs[NTOP];
    __shared__ float logits[NTOP];

    *(float4*)&mpv[tid*4] = *(const float4*)(mp + (size_t)gb*WID + tid*4);
    __syncthreads();

    const int warp = tid >> 5, lane = tid & 31;
    for (int t = warp; t < NTOP; t += 8) {
        const float* wr = tw + (size_t)t * WID;
        float s = 0.0f;
        for (int w = lane; w < WID; w += 32) s = fmaf(mpv[w], wr[w], s);
        #pragma unroll
        for (int o = 16; o > 0; o >>= 1) s += __shfl_down_sync(0xffffffffu, s, o);
        if (lane == 0) logits[t] = s + tb[t];
    }
    __syncthreads();

    if (tid == 0) {
        float m = -1e30f;
        for (int t = 0; t < NTOP; t++) m = fmaxf(m, logits[t]);
        float sum = 0.0f;
        for (int t = 0; t < NTOP; t++) { float e = expf(logits[t] - m); probs[t] = e; sum += e; }
        float inv = 1.0f / sum;
        for (int t = 0; t < NTOP; t++) probs[t] *= inv;
    }
    __syncthreads();

    const int w = tid * 4;
    float4 a = make_float4(0.f, 0.f, 0.f, 0.f);
    for (int t = 0; t < NTOP; t++) {
        float p = probs[t];
        float4 tv = *(const float4*)(table + (size_t)t*WID + w);
        a.x = fmaf(p, tv.x, a.x); a.y = fmaf(p, tv.y, a.y);
        a.z = fmaf(p, tv.z, a.z); a.w = fmaf(p, tv.w, a.w);
    }
    *(float4*)(ue + (size_t)gb*WID + w) = a;
}

// ---------------- final output ----------------
__global__ __launch_bounds__(256) void out_kernel(
    const float* __restrict__ X, const int* __restrict__ in_ids,
    const int* __restrict__ resp_ids, const float* __restrict__ ue,
    float* __restrict__ out)
{
    const int bs = blockIdx.x;
    const int b = bs >> 9, s = bs & 511;
    int g = -1; float c = 0.0f;
    if (s < SIN) {
        int v = in_ids[b*SIN + s];
        if (v > 0)      { g = v - 1;   c = 1.0f; }
        else if (v < 0) { g = -v - 1;  c = 2.0f; }
    } else {
        int v = resp_ids[b*SRES + (s - SIN + 1)];
        if (v == 1)       { g = 6; c = 1.0f; }
        else if (v == -1) { g = 6; c = 2.0f; }
    }
    const int w = threadIdx.x * 4;
    float4 xv = *(const float4*)(X + (size_t)bs*WID + w);
    if (g >= 0) {
        float4 u = *(const float4*)(ue + (size_t)(g*BATCH + b)*WID + w);
        xv.x = fmaf(c, u.x, xv.x); xv.y = fmaf(c, u.y, xv.y);
        xv.z = fmaf(c, u.z, xv.z); xv.w = fmaf(c, u.w, xv.w);
    }
    *(float4*)(out + (size_t)bs*WID + w) = xv;
}

// ---------------- launch ----------------
extern "C" void kernel_launch(void* const* d_in, const int* in_sizes, int n_in,
                              void* d_out, int out_size)
{
    const float* X       = (const float*)d_in[0];
    const int*   in_ids  = (const int*)  d_in[1];
    const int*   resp_ids= (const int*)  d_in[2];
    const float* Wqkv    = (const float*)d_in[3];
    const float* bqkv    = (const float*)d_in[4];
    const float* Wo      = (const float*)d_in[5];
    const float* bo      = (const float*)d_in[6];
    const float* ln1g    = (const float*)d_in[7];
    const float* ln1b    = (const float*)d_in[8];
    const float* W1      = (const float*)d_in[9];
    const float* b1      = (const float*)d_in[10];
    const float* W2      = (const float*)d_in[11];
    const float* b2      = (const float*)d_in[12];
    const float* ln2g    = (const float*)d_in[13];
    const float* ln2b    = (const float*)d_in[14];
    const float* tw      = (const float*)d_in[15];
    const float* tb      = (const float*)d_in[16];
    const float* table   = (const float*)d_in[17];
    float* out = (float*)d_out;

    float *qkv, *ctx, *tmp, *y, *hid, *wr, *mp, *ue;
    cudaGetSymbolAddress((void**)&qkv, g_qkv);
    cudaGetSymbolAddress((void**)&ctx, g_ctx);
    cudaGetSymbolAddress((void**)&tmp, g_tmp);
    cudaGetSymbolAddress((void**)&y,   g_y);
    cudaGetSymbolAddress((void**)&hid, g_hid);
    cudaGetSymbolAddress((void**)&wr,  g_wr);
    cudaGetSymbolAddress((void**)&mp,  g_mp);
    cudaGetSymbolAddress((void**)&ue,  g_ue);

    float* wqkv_r = wr;                 // 3,145,728
    float* wo_r   = wr + 3145728;       // 1,048,576
    float* w1_r   = wr + 4194304;       // 4,194,304
    float* w2_r   = wr + 8388608;       // 4,194,304
    float* xr     = hid;                // rounded X (hid free until step 7)

    const int smem = NSTAGE * STAGE_F * 2 * sizeof(float);
    cudaFuncSetAttribute(mma_gemm, cudaFuncAttributeMaxDynamicSharedMemorySize, smem);

    // 0. pre-round X + all weights to tf32 (one fused pass)
    round_multi<<<8192, 256>>>(
        X,    xr,     (MROWS*WID)/4,
        Wqkv, wqkv_r, (3072*1024)/4,
        Wo,   wo_r,   (1024*1024)/4,
        W1,   w1_r,   (4096*1024)/4,
        W2,   w2_r,   (1024*4096)/4);

    // 1. QKV = Xr @ Wqkv_r^T + bqkv  (output rounded -> attention)
    mma_gemm<<<dim3(3072/BN, MROWS/BM), 256, smem>>>(xr, wqkv_r, bqkv, qkv, MROWS, 3072, 1024, 2);
    // 2. attention (outputs rounded ctx)
    attn_mma_kernel<<<dim3(SEQ/128, BATCH*HEADS), 256>>>(qkv, ctx);
    // 3. proj
    mma_gemm<<<dim3(WID/BN, MROWS/BM), 256, smem>>>(ctx, wo_r, bo, tmp, MROWS, WID, 1024, 0);
    // 4. y = LN(X + proj), plus rounded copy into ctx
    add_ln_kernel<<<MROWS, 256>>>(X, tmp, ln1g, ln1b, y, ctx);
    // 5. FF1 + GELU (output rounded -> FF2)
    mma_gemm<<<dim3(DFF/BN, MROWS/BM), 256, smem>>>(ctx, w1_r, b1, tmp, MROWS, DFF, 1024, 3);
    // 6. FF2
    mma_gemm<<<dim3(WID/BN, MROWS/BM), 256, smem>>>(tmp, w2_r, b2, ctx, MROWS, WID, 4096, 0);
    // 7. hidden = LN(y + FF2)
    add_ln_kernel<<<MROWS, 256>>>(y, ctx, ln2g, ln2b, hid, nullptr);
    // 8-10. topic path + final output
    maxpool_kernel<<<dim3(NGRP, BATCH), 256>>>(hid, in_ids, resp_ids, mp);
    topic_kernel<<<NGRP*BATCH, 256>>>(mp, tw, tb, table, ue);
    out_kernel<<<MROWS, 256>>>(X, in_ids, resp_ids, ue, out);
}

// round 14
// speedup vs baseline: 3.8910x; 1.0946x over previous
#include <cuda_runtime.h>
#include <math.h>
#include <cstdint>

// ---------------- problem constants ----------------
#define BATCH 16
#define SEQ   512
#define SIN   384
#define SRES  129
#define WID   1024
#define HEADS 16
#define DHEAD 64
#define DFF   4096
#define NTOP  50
#define NGRP  7
#define MROWS (BATCH*SEQ)   // 8192

// ---------------- scratch ----------------
__device__ float g_qkv[(size_t)MROWS * 3072];
__device__ float g_ctx[(size_t)MROWS * WID];
__device__ float g_tmp[(size_t)MROWS * DFF];
__device__ float g_y  [(size_t)MROWS * WID];
__device__ float g_hid[(size_t)MROWS * WID];      // rounded+permuted X early, hidden late
__device__ float g_wr [12582912];                  // rounded+permuted weights
__device__ float g_mp [NGRP * BATCH * WID];
__device__ float g_ue [NGRP * BATCH * WID];

// round-to-nearest tf32
__device__ __forceinline__ uint32_t f2tf(float x) {
    uint32_t r;
    asm("cvt.rna.tf32.f32 %0, %1;" : "=r"(r) : "f"(x));
    return r;
}
__device__ __forceinline__ float rtf(float x) { return __uint_as_float(f2tf(x)); }

__device__ __forceinline__ void mma_tf32(float* c, const uint32_t* a, const uint32_t* b) {
    asm volatile(
        "mma.sync.aligned.m16n8k8.row.col.f32.tf32.tf32.f32 "
        "{%0,%1,%2,%3}, {%4,%5,%6,%7}, {%8,%9}, {%0,%1,%2,%3};"
        : "+f"(c[0]), "+f"(c[1]), "+f"(c[2]), "+f"(c[3])
        : "r"(a[0]), "r"(a[1]), "r"(a[2]), "r"(a[3]), "r"(b[0]), "r"(b[1]));
}

__device__ __forceinline__ void cpa16(void* dst, const float* src) {
    uint32_t d = (uint32_t)__cvta_generic_to_shared(dst);
    asm volatile("cp.async.cg.shared.global [%0], [%1], 16;" :: "r"(d), "l"(src));
}

// ---------------- fused multi-tensor tf32 round + K-group permute ----------------
// permutation per 8-group: stored[2j] = orig[j], stored[2j+1] = orig[j+4]
__global__ __launch_bounds__(256) void round_perm_multi(
    const float* s0, float* d0, int n0,
    const float* s1, float* d1, int n1,
    const float* s2, float* d2, int n2,
    const float* s3, float* d3, int n3,
    const float* s4, float* d4, int n4)   // counts in float8 units
{
    int total = n0 + n1 + n2 + n3 + n4;
    for (int idx = blockIdx.x * 256 + threadIdx.x; idx < total; idx += gridDim.x * 256) {
        int i = idx;
        const float* s; float* d;
        if (i < n0) { s = s0; d = d0; }
        else { i -= n0;
            if (i < n1) { s = s1; d = d1; }
            else { i -= n1;
                if (i < n2) { s = s2; d = d2; }
                else { i -= n2;
                    if (i < n3) { s = s3; d = d3; }
                    else { i -= n3; s = s4; d = d4; } } } }
        float4 lo = *(const float4*)(s + (size_t)i * 8);
        float4 hi = *(const float4*)(s + (size_t)i * 8 + 4);
        float4 w0, w1;
        w0.x = rtf(lo.x); w0.y = rtf(hi.x); w0.z = rtf(lo.y); w0.w = rtf(hi.y);
        w1.x = rtf(lo.z); w1.y = rtf(hi.z); w1.z = rtf(lo.w); w1.w = rtf(hi.w);
        *(float4*)(d + (size_t)i * 8)     = w0;
        *(float4*)(d + (size_t)i * 8 + 4) = w1;
    }
}

// ================= TF32 tensor-core GEMM (permuted-K operands) =================
// C[M,N] = A[M,K] @ B[N,K]^T + bias. 128x128x32 tile, 256 thr, warp 64x32 (4x4 m16n8k8).
// Smem: 32-word rows, XOR swizzle (chunk ^ 2*(row&3)) -> conflict-free 16B stores
// and float2 fragment loads. mode: bit0=GELU, bit1=round out, bit2=permute out cols.
#define BM 128
#define BN 128
#define BK 32
#define NSTAGE 3
#define STAGE_F (BM * BK)    // 4096 floats per operand per stage

__global__ __launch_bounds__(256, 2) void mma_gemm(
    const float* __restrict__ A, const float* __restrict__ Bw,
    const float* __restrict__ bias, float* __restrict__ C,
    int M, int N, int K, int mode)
{
    extern __shared__ float smbuf[];
    float* As = smbuf;
    float* Bs = smbuf + NSTAGE * STAGE_F;

    const int tid  = threadIdx.x;
    const int m0   = blockIdx.y * BM;
    const int n0   = blockIdx.x * BN;
    const int warp = tid >> 5, lane = tid & 31;
    const int g    = lane >> 2, tig = lane & 3;
    const int mw   = (warp >> 2) * 64;
    const int nw   = (warp & 3) * 32;

    float acc[4][4][4];
    #pragma unroll
    for (int mi = 0; mi < 4; mi++)
        #pragma unroll
        for (int ni = 0; ni < 4; ni++)
            #pragma unroll
            for (int r = 0; r < 4; r++) acc[mi][ni][r] = 0.0f;

    const int kiters = K / BK;

    // fragment address precompute: phys = row*32 + 4*((kk/4 + t2)^swz) + tl
    //                                   = rbase(row) + koff(kk)   [no-carry split]
    const int swz = (g & 3) << 1;
    const int t2  = tig >> 1;
    const int tl  = (tig & 1) << 1;
    int koff[4];
    #pragma unroll
    for (int j = 0; j < 4; j++) koff[j] = (((j << 1) ^ swz) << 2);
    int rA[4], rB[4];
    #pragma unroll
    for (int mi = 0; mi < 4; mi++) rA[mi] = (mw + mi * 16 + g) * 32 + 4 * t2 + tl;
    #pragma unroll
    for (int ni = 0; ni < 4; ni++) rB[ni] = (nw + ni * 8 + g) * 32 + 4 * t2 + tl;

    // staging: 1024 16B-chunks per operand tile, 4 per thread, swizzled dst
    #pragma unroll
    for (int s = 0; s < NSTAGE - 1; s++) {
        const int k0 = s * BK;
        #pragma unroll
        for (int i = 0; i < 4; i++) {
            int c = tid + (i << 8);
            int row = c >> 3, ch = c & 7;
            int dst = row * 32 + ((ch ^ ((row & 3) << 1)) << 2);
            cpa16(As + s * STAGE_F + dst, A  + (size_t)(m0 + row) * K + k0 + ch * 4);
            cpa16(Bs + s * STAGE_F + dst, Bw + (size_t)(n0 + row) * K + k0 + ch * 4);
        }
        asm volatile("cp.async.commit_group;");
    }

    for (int kt = 0; kt < kiters; kt++) {
        if (kt + NSTAGE - 1 < kiters) {
            const int s = (kt + NSTAGE - 1) % NSTAGE;
            const int k0 = (kt + NSTAGE - 1) * BK;
            #pragma unroll
            for (int i = 0; i < 4; i++) {
                int c = tid + (i << 8);
                int row = c >> 3, ch = c & 7;
                int dst = row * 32 + ((ch ^ ((row & 3) << 1)) << 2);
                cpa16(As + s * STAGE_F + dst, A  + (size_t)(m0 + row) * K + k0 + ch * 4);
                cpa16(Bs + s * STAGE_F + dst, Bw + (size_t)(n0 + row) * K + k0 + ch * 4);
            }
        }
        asm volatile("cp.async.commit_group;");
        asm volatile("cp.async.wait_group %0;" :: "n"(NSTAGE - 1));
        __syncthreads();

        const float* as = As + (kt % NSTAGE) * STAGE_F;
        const float* bs = Bs + (kt % NSTAGE) * STAGE_F;

        #pragma unroll
        for (int j = 0; j < 4; j++) {          // 4 k8-chunks per BK=32
            uint32_t af[4][4], bf[4][2];
            #pragma unroll
            for (int mi = 0; mi < 4; mi++) {
                float2 x1 = *(const float2*)(as + rA[mi] + koff[j]);
                float2 x2 = *(const float2*)(as + rA[mi] + 256 + koff[j]);  // +8 rows
                af[mi][0] = __float_as_uint(x1.x);
                af[mi][2] = __float_as_uint(x1.y);
                af[mi][1] = __float_as_uint(x2.x);
                af[mi][3] = __float_as_uint(x2.y);
            }
            #pragma unroll
            for (int ni = 0; ni < 4; ni++) {
                float2 y = *(const float2*)(bs + rB[ni] + koff[j]);
                bf[ni][0] = __float_as_uint(y.x);
                bf[ni][1] = __float_as_uint(y.y);
            }
            #pragma unroll
            for (int mi = 0; mi < 4; mi++)
                #pragma unroll
                for (int ni = 0; ni < 4; ni++)
                    mma_tf32(acc[mi][ni], af[mi], bf[ni]);
        }
        __syncthreads();
    }

    const bool dogelu  = (mode & 1) != 0;
    const bool doround = (mode & 2) != 0;
    const bool doperm  = (mode & 4) != 0;
    const int  p0 = (tig < 2) ? 4 * tig     : 4 * tig - 7;   // permuted pos of orig col 2t
    const int  p1 = (tig < 2) ? 4 * tig + 2 : 4 * tig - 5;   // permuted pos of orig col 2t+1
    #pragma unroll
    for (int ni = 0; ni < 4; ni++) {
        const int gb = n0 + nw + ni * 8;
        const int cc = gb + 2 * tig;
        const float bv0 = bias[cc], bv1 = bias[cc + 1];
        #pragma unroll
        for (int mi = 0; mi < 4; mi++) {
            const int r0 = m0 + mw + mi * 16 + g;
            float v00 = acc[mi][ni][0] + bv0;
            float v01 = acc[mi][ni][1] + bv1;
            float v10 = acc[mi][ni][2] + bv0;
            float v11 = acc[mi][ni][3] + bv1;
            if (dogelu) {
                v00 = 0.5f * v00 * (1.0f + erff(v00 * 0.70710678118654752f));
                v01 = 0.5f * v01 * (1.0f + erff(v01 * 0.70710678118654752f));
                v10 = 0.5f * v10 * (1.0f + erff(v10 * 0.70710678118654752f));
                v11 = 0.5f * v11 * (1.0f + erff(v11 * 0.70710678118654752f));
            }
            if (doround) {
                v00 = rtf(v00); v01 = rtf(v01); v10 = rtf(v10); v11 = rtf(v11);
            }
            if (doperm) {
                C[(size_t)r0 * N + gb + p0]       = v00;
                C[(size_t)r0 * N + gb + p1]       = v01;
                C[(size_t)(r0 + 8) * N + gb + p0] = v10;
                C[(size_t)(r0 + 8) * N + gb + p1] = v11;
            } else {
                *(float2*)(C + (size_t)r0 * N + cc)       = make_float2(v00, v01);
                *(float2*)(C + (size_t)(r0 + 8) * N + cc) = make_float2(v10, v11);
            }
        }
    }
}

// ================= tensor-core flash attention (qkv tf32-rounded, d-axis permuted) ==
// d-permutation cancels in Q@K^T (both operands permuted); V's permuted d-labels
// pass through to ctx columns, which is exactly the layout proj's A operand needs.
#define QP 72   // pitch for Qs/Ks/Vs: conflict-free float2 frag loads over d
#define PP 68   // pitch for Ps: conflict-free scalar loads over s

__global__ __launch_bounds__(256, 2) void attn_mma_kernel(
    const float* __restrict__ qkv, float* __restrict__ ctx)
{
    __shared__ float Qs[128][QP];
    __shared__ float Ks[64][QP];
    __shared__ float Vs[64][QP];
    __shared__ float Ps[128][PP];

    const int bh = blockIdx.y;
    const int b = bh >> 4, h = bh & 15;
    const int q0 = blockIdx.x * 128;
    const int tid = threadIdx.x;
    const int warp = tid >> 5, lane = tid & 31;
    const int g = lane >> 2, t = lane & 3;
    const int mw = warp * 16;

    // stage Q (scaled by 1/8, exact)
    #pragma unroll
    for (int i = 0; i < 8; i++) {
        int idx = tid + i * 256;
        int row = idx >> 4, c4 = (idx & 15) * 4;
        float4 v = *(const float4*)(qkv + (size_t)(b*SEQ + q0 + row) * 3072 + h*DHEAD + c4);
        v.x *= 0.125f; v.y *= 0.125f; v.z *= 0.125f; v.w *= 0.125f;
        *(float4*)&Qs[row][c4] = v;
    }

    float o[8][4];
    #pragma unroll
    for (int nt = 0; nt < 8; nt++)
        #pragma unroll
        for (int r = 0; r < 4; r++) o[nt][r] = 0.0f;
    float m0 = -1e30f, m1 = -1e30f, l0 = 0.0f, l1 = 0.0f;

    for (int kb = 0; kb < SEQ; kb += 64) {
        __syncthreads();
        #pragma unroll
        for (int i = 0; i < 4; i++) {
            int idx = tid + i * 256;
            int row = idx >> 4, c4 = (idx & 15) * 4;
            const float* base = qkv + (size_t)(b*SEQ + kb + row) * 3072 + h*DHEAD + c4;
            *(float4*)&Ks[row][c4] = *(const float4*)(base + 1024);
            *(float4*)&Vs[row][c4] = *(const float4*)(base + 2048);
        }
        __syncthreads();

        // ---- S = Q @ K^T (d permuted identically in Q and K) ----
        float sacc[8][4];
        #pragma unroll
        for (int nt = 0; nt < 8; nt++)
            #pragma unroll
            for (int r = 0; r < 4; r++) sacc[nt][r] = 0.0f;

        #pragma unroll
        for (int kt = 0; kt < 8; kt++) {
            uint32_t af[4];
            float2 q1 = *(const float2*)&Qs[mw + g][kt*8 + 2*t];
            float2 q2 = *(const float2*)&Qs[mw + g + 8][kt*8 + 2*t];
            af[0] = __float_as_uint(q1.x); af[2] = __float_as_uint(q1.y);
            af[1] = __float_as_uint(q2.x); af[3] = __float_as_uint(q2.y);
            #pragma unroll
            for (int nt = 0; nt < 8; nt++) {
                uint32_t bf[2];
                float2 kv = *(const float2*)&Ks[nt*8 + g][kt*8 + 2*t];
                bf[0] = __float_as_uint(kv.x); bf[1] = __float_as_uint(kv.y);
                mma_tf32(sacc[nt], af, bf);
            }
        }

        // ---- online softmax ----
        float rmax0 = -1e30f, rmax1 = -1e30f;
        #pragma unroll
        for (int nt = 0; nt < 8; nt++) {
            rmax0 = fmaxf(rmax0, fmaxf(sacc[nt][0], sacc[nt][1]));
            rmax1 = fmaxf(rmax1, fmaxf(sacc[nt][2], sacc[nt][3]));
        }
        #pragma unroll
        for (int d = 1; d < 4; d <<= 1) {
            rmax0 = fmaxf(rmax0, __shfl_xor_sync(0xffffffffu, rmax0, d));
            rmax1 = fmaxf(rmax1, __shfl_xor_sync(0xffffffffu, rmax1, d));
        }
        float m0n = fmaxf(m0, rmax0), m1n = fmaxf(m1, rmax1);
        float c0 = __expf(m0 - m0n), c1 = __expf(m1 - m1n);
        m0 = m0n; m1 = m1n;

        float sum0 = 0.0f, sum1 = 0.0f;
        #pragma unroll
        for (int nt = 0; nt < 8; nt++) {
            sacc[nt][0] = __expf(sacc[nt][0] - m0);
            sacc[nt][1] = __expf(sacc[nt][1] - m0);
            sacc[nt][2] = __expf(sacc[nt][2] - m1);
            sacc[nt][3] = __expf(sacc[nt][3] - m1);
            sum0 += sacc[nt][0] + sacc[nt][1];
            sum1 += sacc[nt][2] + sacc[nt][3];
        }
        #pragma unroll
        for (int d = 1; d < 4; d <<= 1) {
            sum0 += __shfl_xor_sync(0xffffffffu, sum0, d);
            sum1 += __shfl_xor_sync(0xffffffffu, sum1, d);
        }
        l0 = l0 * c0 + sum0;
        l1 = l1 * c1 + sum1;
        #pragma unroll
        for (int nt = 0; nt < 8; nt++) {
            o[nt][0] *= c0; o[nt][1] *= c0;
            o[nt][2] *= c1; o[nt][3] *= c1;
        }

        // write P (rounded once; s-axis unpermuted)
        #pragma unroll
        for (int nt = 0; nt < 8; nt++) {
            *(float2*)&Ps[mw + g][nt*8 + 2*t]     = make_float2(rtf(sacc[nt][0]), rtf(sacc[nt][1]));
            *(float2*)&Ps[mw + g + 8][nt*8 + 2*t] = make_float2(rtf(sacc[nt][2]), rtf(sacc[nt][3]));
        }
        __syncwarp();

        // ---- O += P @ V (contraction over s: scalar frag loads, as before) ----
        #pragma unroll
        for (int kt = 0; kt < 8; kt++) {
            uint32_t af[4];
            const float* p  = &Ps[mw + g][kt*8 + t];
            const float* p2 = p + 8 * PP;
            af[0] = __float_as_uint(p[0]);  af[2] = __float_as_uint(p[4]);
            af[1] = __float_as_uint(p2[0]); af[3] = __float_as_uint(p2[4]);
            #pragma unroll
            for (int nt = 0; nt < 8; nt++) {
                uint32_t bf[2];
                bf[0] = __float_as_uint(Vs[kt*8 + t][nt*8 + g]);
                bf[1] = __float_as_uint(Vs[kt*8 + t + 4][nt*8 + g]);
                mma_tf32(o[nt], af, bf);
            }
        }
    }

    // output (cols carry V's permuted d-labels -> exactly what proj expects)
    float inv0 = 1.0f / l0, inv1 = 1.0f / l1;
    const int r0 = b*SEQ + q0 + mw + g;
    const int cbase = h*DHEAD + 2*t;
    #pragma unroll
    for (int nt = 0; nt < 8; nt++) {
        *(float2*)(ctx + (size_t)r0 * WID + cbase + nt*8) =
            make_float2(rtf(o[nt][0]*inv0), rtf(o[nt][1]*inv0));
        *(float2*)(ctx + (size_t)(r0 + 8) * WID + cbase + nt*8) =
            make_float2(rtf(o[nt][2]*inv1), rtf(o[nt][3]*inv1));
    }
}

// ---------------- residual add + LayerNorm (+ optional rounded PERMUTED copy) -------
__global__ __launch_bounds__(256) void add_ln_kernel(
    const float* __restrict__ resid, const float* __restrict__ x,
    const float* __restrict__ gg, const float* __restrict__ bb,
    float* __restrict__ out, float* __restrict__ outr)
{
    __shared__ float2 sm[8];
    const size_t row = blockIdx.x;
    const int tid = threadIdx.x;

    float4 r = *(const float4*)(resid + row*WID + tid*4);
    float4 v = *(const float4*)(x     + row*WID + tid*4);
    float4 tv;
    tv.x = r.x + v.x; tv.y = r.y + v.y; tv.z = r.z + v.z; tv.w = r.w + v.w;

    float s = tv.x + tv.y + tv.z + tv.w;
    float qq = tv.x*tv.x + tv.y*tv.y + tv.z*tv.z + tv.w*tv.w;

    int lane = tid & 31, warp = tid >> 5;
    #pragma unroll
    for (int o = 16; o > 0; o >>= 1) {
        s  += __shfl_down_sync(0xffffffffu, s,  o);
        qq += __shfl_down_sync(0xffffffffu, qq, o);
    }
    if (lane == 0) sm[warp] = make_float2(s, qq);
    __syncthreads();
    if (warp == 0) {
        float2 w2 = (lane < 8) ? sm[lane] : make_float2(0.f, 0.f);
        #pragma unroll
        for (int o = 4; o > 0; o >>= 1) {
            w2.x += __shfl_down_sync(0xffffffffu, w2.x, o);
            w2.y += __shfl_down_sync(0xffffffffu, w2.y, o);
        }
        if (lane == 0) sm[0] = w2;
    }
    __syncthreads();
    float mean = sm[0].x * (1.0f/WID);
    float var  = sm[0].y * (1.0f/WID) - mean*mean;
    float rstd = rsqrtf(var + 1e-5f);

    float4 g4 = *(const float4*)(gg + tid*4);
    float4 b4 = *(const float4*)(bb + tid*4);
    float4 o;
    o.x = (tv.x - mean)*rstd*g4.x + b4.x;
    o.y = (tv.y - mean)*rstd*g4.y + b4.y;
    o.z = (tv.z - mean)*rstd*g4.z + b4.z;
    o.w = (tv.w - mean)*rstd*g4.w + b4.w;
    *(float4*)(out + row*WID + tid*4) = o;
    if (outr) {
        // permuted scatter: group = tid>>1; even tid holds orig 0..3 -> pos 0,2,4,6
        float* d = outr + row*WID + (size_t)(tid >> 1) * 8 + (tid & 1);
        d[0] = rtf(o.x); d[2] = rtf(o.y); d[4] = rtf(o.z); d[6] = rtf(o.w);
    }
}

// ---------------- masked max-pool ----------------
__global__ __launch_bounds__(256) void maxpool_kernel(
    const float* __restrict__ hidden, const int* __restrict__ in_ids,
    const int* __restrict__ resp_ids, float* __restrict__ mp)
{
    const int g = blockIdx.x;
    const int b = blockIdx.y;
    const int tid = threadIdx.x;
    __shared__ unsigned char flag[SEQ];

    for (int s = tid; s < SEQ; s += 256) {
        bool f = false;
        if (g < 6) { if (s < SIN) f = (in_ids[b*SIN + s] == g + 1); }
        else       { if (s >= SIN) f = (resp_ids[b*SRES + (s - SIN + 1)] == 1); }
        flag[s] = f ? 1 : 0;
    }
    __syncthreads();

    const int w = tid * 4;
    float4 vm = make_float4(0.f, 0.f, 0.f, 0.f);
    for (int s = 0; s < SEQ; s++) {
        if (flag[s]) {
            float4 hv = *(const float4*)(hidden + (size_t)(b*SEQ + s)*WID + w);
            vm.x = fmaxf(vm.x, hv.x); vm.y = fmaxf(vm.y, hv.y);
            vm.z = fmaxf(vm.z, hv.z); vm.w = fmaxf(vm.w, hv.w);
        }
    }
    *(float4*)(mp + (size_t)(g*BATCH + b)*WID + w) = vm;
}

// ---------------- topic softmax + gather ----------------
__global__ __launch_bounds__(256) void topic_kernel(
    const float* __restrict__ mp, const float* __restrict__ tw,
    const float* __restrict__ tb, const float* __restrict__ table,
    float* __restrict__ ue)
{
    const int gb = blockIdx.x;
    const int tid = threadIdx.x;
    __shared__ float mpv[WID];
    __shared__ float probs[NTOP];
    __shared__ float logits[NTOP];

    *(float4*)&mpv[tid*4] = *(const float4*)(mp + (size_t)gb*WID + tid*4);
    __syncthreads();

    const int warp = tid >> 5, lane = tid & 31;
    for (int t = warp; t < NTOP; t += 8) {
        const float* wr = tw + (size_t)t * WID;
        float s = 0.0f;
        for (int w = lane; w < WID; w += 32) s = fmaf(mpv[w], wr[w], s);
        #pragma unroll
        for (int o = 16; o > 0; o >>= 1) s += __shfl_down_sync(0xffffffffu, s, o);
        if (lane == 0) logits[t] = s + tb[t];
    }
    __syncthreads();

    if (tid == 0) {
        float m = -1e30f;
        for (int t = 0; t < NTOP; t++) m = fmaxf(m, logits[t]);
        float sum = 0.0f;
        for (int t = 0; t < NTOP; t++) { float e = expf(logits[t] - m); probs[t] = e; sum += e; }
        float inv = 1.0f / sum;
        for (int t = 0; t < NTOP; t++) probs[t] *= inv;
    }
    __syncthreads();

    const int w = tid * 4;
    float4 a = make_float4(0.f, 0.f, 0.f, 0.f);
    for (int t = 0; t < NTOP; t++) {
        float p = probs[t];
        float4 tv = *(const float4*)(table + (size_t)t*WID + w);
        a.x = fmaf(p, tv.x, a.x); a.y = fmaf(p, tv.y, a.y);
        a.z = fmaf(p, tv.z, a.z); a.w = fmaf(p, tv.w, a.w);
    }
    *(float4*)(ue + (size_t)gb*WID + w) = a;
}

// ---------------- final output ----------------
__global__ __launch_bounds__(256) void out_kernel(
    const float* __restrict__ X, const int* __restrict__ in_ids,
    const int* __restrict__ resp_ids, const float* __restrict__ ue,
    float* __restrict__ out)
{
    const int bs = blockIdx.x;
    const int b = bs >> 9, s = bs & 511;
    int g = -1; float c = 0.0f;
    if (s < SIN) {
        int v = in_ids[b*SIN + s];
        if (v > 0)      { g = v - 1;   c = 1.0f; }
        else if (v < 0) { g = -v - 1;  c = 2.0f; }
    } else {
        int v = resp_ids[b*SRES + (s - SIN + 1)];
        if (v == 1)       { g = 6; c = 1.0f; }
        else if (v == -1) { g = 6; c = 2.0f; }
    }
    const int w = threadIdx.x * 4;
    float4 xv = *(const float4*)(X + (size_t)bs*WID + w);
    if (g >= 0) {
        float4 u = *(const float4*)(ue + (size_t)(g*BATCH + b)*WID + w);
        xv.x = fmaf(c, u.x, xv.x); xv.y = fmaf(c, u.y, xv.y);
        xv.z = fmaf(c, u.z, xv.z); xv.w = fmaf(c, u.w, xv.w);
    }
    *(float4*)(out + (size_t)bs*WID + w) = xv;
}

// ---------------- launch ----------------
extern "C" void kernel_launch(void* const* d_in, const int* in_sizes, int n_in,
                              void* d_out, int out_size)
{
    const float* X       = (const float*)d_in[0];
    const int*   in_ids  = (const int*)  d_in[1];
    const int*   resp_ids= (const int*)  d_in[2];
    const float* Wqkv    = (const float*)d_in[3];
    const float* bqkv    = (const float*)d_in[4];
    const float* Wo      = (const float*)d_in[5];
    const float* bo      = (const float*)d_in[6];
    const float* ln1g    = (const float*)d_in[7];
    const float* ln1b    = (const float*)d_in[8];
    const float* W1      = (const float*)d_in[9];
    const float* b1      = (const float*)d_in[10];
    const float* W2      = (const float*)d_in[11];
    const float* b2      = (const float*)d_in[12];
    const float* ln2g    = (const float*)d_in[13];
    const float* ln2b    = (const float*)d_in[14];
    const float* tw      = (const float*)d_in[15];
    const float* tb      = (const float*)d_in[16];
    const float* table   = (const float*)d_in[17];
    float* out = (float*)d_out;

    float *qkv, *ctx, *tmp, *y, *hid, *wr, *mp, *ue;
    cudaGetSymbolAddress((void**)&qkv, g_qkv);
    cudaGetSymbolAddress((void**)&ctx, g_ctx);
    cudaGetSymbolAddress((void**)&tmp, g_tmp);
    cudaGetSymbolAddress((void**)&y,   g_y);
    cudaGetSymbolAddress((void**)&hid, g_hid);
    cudaGetSymbolAddress((void**)&wr,  g_wr);
    cudaGetSymbolAddress((void**)&mp,  g_mp);
    cudaGetSymbolAddress((void**)&ue,  g_ue);

    float* wqkv_r = wr;                 // 3,145,728
    float* wo_r   = wr + 3145728;       // 1,048,576
    float* w1_r   = wr + 4194304;       // 4,194,304
    float* w2_r   = wr + 8388608;       // 4,194,304
    float* xr     = hid;                // rounded+permuted X (hid free until step 7)

    const int smem = NSTAGE * STAGE_F * 2 * sizeof(float);   // 98,304 B
    cudaFuncSetAttribute(mma_gemm, cudaFuncAttributeMaxDynamicSharedMemorySize, smem);

    // 0. round+permute X and all weights (counts in float8 units)
    round_perm_multi<<<8192, 256>>>(
        X,    xr,     (MROWS*WID)/8,
        Wqkv, wqkv_r, (3072*1024)/8,
        Wo,   wo_r,   (1024*1024)/8,
        W1,   w1_r,   (4096*1024)/8,
        W2,   w2_r,   (1024*4096)/8);

    // 1. QKV (round + permute output cols -> attention reads permuted d)
    mma_gemm<<<dim3(3072/BN, MROWS/BM), 256, smem>>>(xr, wqkv_r, bqkv, qkv, MROWS, 3072, 1024, 6);
    // 2. attention (ctx cols inherit permuted d-labels, rounded)
    attn_mma_kernel<<<dim3(SEQ/128, BATCH*HEADS), 256>>>(qkv, ctx);
    // 3. proj
    mma_gemm<<<dim3(WID/BN, MROWS/BM), 256, smem>>>(ctx, wo_r, bo, tmp, MROWS, WID, 1024, 0);
    // 4. y = LN(X + proj), plus rounded+permuted copy into ctx
    add_ln_kernel<<<MROWS, 256>>>(X, tmp, ln1g, ln1b, y, ctx);
    // 5. FF1 + GELU (round + permute -> FF2)
    mma_gemm<<<dim3(DFF/BN, MROWS/BM), 256, smem>>>(ctx, w1_r, b1, tmp, MROWS, DFF, 1024, 7);
    // 6. FF2
    mma_gemm<<<dim3(WID/BN, MROWS/BM), 256, smem>>>(tmp, w2_r, b2, ctx, MROWS, WID, 4096, 0);
    // 7. hidden = LN(y + FF2)
    add_ln_kernel<<<MROWS, 256>>>(y, ctx, ln2g, ln2b, hid, nullptr);
    // 8-10. topic path + final output
    maxpool_kernel<<<dim3(NGRP, BATCH), 256>>>(hid, in_ids, resp_ids, mp);
    topic_kernel<<<NGRP*BATCH, 256>>>(mp, tw, tb, table, ue);
    out_kernel<<<MROWS, 256>>>(X, in_ids, resp_ids, ue, out);
}

// round 15
// speedup vs baseline: 4.2329x; 1.0879x over previous
#include <cuda_runtime.h>
#include <math.h>
#include <cstdint>

// ---------------- problem constants ----------------
#define BATCH 16
#define SEQ   512
#define SIN   384
#define SRES  129
#define WID   1024
#define HEADS 16
#define DHEAD 64
#define DFF   4096
#define NTOP  50
#define NGRP  7
#define MROWS (BATCH*SEQ)   // 8192

// ---------------- scratch ----------------
__device__ float g_qkv[(size_t)MROWS * 3072];
__device__ float g_ctx[(size_t)MROWS * WID];
__device__ float g_tmp[(size_t)MROWS * DFF];
__device__ float g_y  [(size_t)MROWS * WID];
__device__ float g_hid[(size_t)MROWS * WID];      // rounded+permuted X early, hidden late
__device__ float g_wr [12582912];                  // rounded+permuted weights
__device__ float g_mp [NGRP * BATCH * WID];
__device__ float g_ue [NGRP * BATCH * WID];

// round-to-nearest tf32
__device__ __forceinline__ uint32_t f2tf(float x) {
    uint32_t r;
    asm("cvt.rna.tf32.f32 %0, %1;" : "=r"(r) : "f"(x));
    return r;
}
__device__ __forceinline__ float rtf(float x) { return __uint_as_float(f2tf(x)); }

__device__ __forceinline__ void mma_tf32(float* c, const uint32_t* a, const uint32_t* b) {
    asm volatile(
        "mma.sync.aligned.m16n8k8.row.col.f32.tf32.tf32.f32 "
        "{%0,%1,%2,%3}, {%4,%5,%6,%7}, {%8,%9}, {%0,%1,%2,%3};"
        : "+f"(c[0]), "+f"(c[1]), "+f"(c[2]), "+f"(c[3])
        : "r"(a[0]), "r"(a[1]), "r"(a[2]), "r"(a[3]), "r"(b[0]), "r"(b[1]));
}

__device__ __forceinline__ void cpa16(void* dst, const float* src) {
    uint32_t d = (uint32_t)__cvta_generic_to_shared(dst);
    asm volatile("cp.async.cg.shared.global [%0], [%1], 16;" :: "r"(d), "l"(src));
}

// ---------------- fused multi-tensor tf32 round + K-group permute ----------------
// permutation per 8-group: stored[2j] = orig[j], stored[2j+1] = orig[j+4]
__global__ __launch_bounds__(256) void round_perm_multi(
    const float* s0, float* d0, int n0,
    const float* s1, float* d1, int n1,
    const float* s2, float* d2, int n2,
    const float* s3, float* d3, int n3,
    const float* s4, float* d4, int n4)   // counts in float8 units
{
    int total = n0 + n1 + n2 + n3 + n4;
    for (int idx = blockIdx.x * 256 + threadIdx.x; idx < total; idx += gridDim.x * 256) {
        int i = idx;
        const float* s; float* d;
        if (i < n0) { s = s0; d = d0; }
        else { i -= n0;
            if (i < n1) { s = s1; d = d1; }
            else { i -= n1;
                if (i < n2) { s = s2; d = d2; }
                else { i -= n2;
                    if (i < n3) { s = s3; d = d3; }
                    else { i -= n3; s = s4; d = d4; } } } }
        float4 lo = *(const float4*)(s + (size_t)i * 8);
        float4 hi = *(const float4*)(s + (size_t)i * 8 + 4);
        float4 w0, w1;
        w0.x = rtf(lo.x); w0.y = rtf(hi.x); w0.z = rtf(lo.y); w0.w = rtf(hi.y);
        w1.x = rtf(lo.z); w1.y = rtf(hi.z); w1.z = rtf(lo.w); w1.w = rtf(hi.w);
        *(float4*)(d + (size_t)i * 8)     = w0;
        *(float4*)(d + (size_t)i * 8 + 4) = w1;
    }
}

// ================= TF32 tensor-core GEMM (permuted-K operands) =================
// C[M,N] = A[M,K] @ B[N,K]^T + bias. 128x128x32 block tile, 128 threads (4 warps),
// warp tile 64x64 (4x8 m16n8k8). Single __syncthreads per K-iter; prefetch after
// the barrier. XOR-swizzled 32-word smem rows. mode: bit0=GELU, bit1=round,
// bit2=permute output cols.
#define BM 128
#define BN 128
#define BK 32
#define NSTAGE 3
#define STAGE_F (BM * BK)    // 4096 floats per operand per stage

__global__ __launch_bounds__(128, 2) void mma_gemm(
    const float* __restrict__ A, const float* __restrict__ Bw,
    const float* __restrict__ bias, float* __restrict__ C,
    int M, int N, int K, int mode)
{
    extern __shared__ float smbuf[];
    float* As = smbuf;
    float* Bs = smbuf + NSTAGE * STAGE_F;

    const int tid  = threadIdx.x;
    const int m0   = blockIdx.y * BM;
    const int n0   = blockIdx.x * BN;
    const int warp = tid >> 5, lane = tid & 31;
    const int g    = lane >> 2, tig = lane & 3;
    const int mw   = (warp >> 1) * 64;   // 0 or 64
    const int nw   = (warp & 1) * 64;    // 0 or 64

    float acc[4][8][4];
    #pragma unroll
    for (int mi = 0; mi < 4; mi++)
        #pragma unroll
        for (int ni = 0; ni < 8; ni++)
            #pragma unroll
            for (int r = 0; r < 4; r++) acc[mi][ni][r] = 0.0f;

    const int kiters = K / BK;

    // fragment address precompute: phys = row*32 + 4*((kk/4 + t2)^swz) + tl
    const int swz = (g & 3) << 1;
    const int t2  = tig >> 1;
    const int tl  = (tig & 1) << 1;
    int koff[4];
    #pragma unroll
    for (int j = 0; j < 4; j++) koff[j] = (((j << 1) ^ swz) << 2);
    int rA[4], rB[8];
    #pragma unroll
    for (int mi = 0; mi < 4; mi++) rA[mi] = (mw + mi * 16 + g) * 32 + 4 * t2 + tl;
    #pragma unroll
    for (int ni = 0; ni < 8; ni++) rB[ni] = (nw + ni * 8 + g) * 32 + 4 * t2 + tl;

    // staging: 1024 16B-chunks per operand tile, 8 per thread (128 threads)
    #pragma unroll
    for (int s = 0; s < NSTAGE - 1; s++) {
        const int k0 = s * BK;
        #pragma unroll
        for (int i = 0; i < 8; i++) {
            int c = tid + (i << 7);
            int row = c >> 3, ch = c & 7;
            int dst = row * 32 + ((ch ^ ((row & 3) << 1)) << 2);
            cpa16(As + s * STAGE_F + dst, A  + (size_t)(m0 + row) * K + k0 + ch * 4);
            cpa16(Bs + s * STAGE_F + dst, Bw + (size_t)(n0 + row) * K + k0 + ch * 4);
        }
        asm volatile("cp.async.commit_group;");
    }

    for (int kt = 0; kt < kiters; kt++) {
        asm volatile("cp.async.wait_group %0;" :: "n"(NSTAGE - 2));
        __syncthreads();

        // prefetch stage kt+2 into buffer (kt-1)%3 — consumed last iteration,
        // and every thread passed the barrier above after finishing it.
        const int ps = kt + NSTAGE - 1;
        if (ps < kiters) {
            const int s = ps % NSTAGE;
            const int k0 = ps * BK;
            #pragma unroll
            for (int i = 0; i < 8; i++) {
                int c = tid + (i << 7);
                int row = c >> 3, ch = c & 7;
                int dst = row * 32 + ((ch ^ ((row & 3) << 1)) << 2);
                cpa16(As + s * STAGE_F + dst, A  + (size_t)(m0 + row) * K + k0 + ch * 4);
                cpa16(Bs + s * STAGE_F + dst, Bw + (size_t)(n0 + row) * K + k0 + ch * 4);
            }
        }
        asm volatile("cp.async.commit_group;");   // always (empty in tail)

        const float* as = As + (kt % NSTAGE) * STAGE_F;
        const float* bs = Bs + (kt % NSTAGE) * STAGE_F;

        #pragma unroll
        for (int j = 0; j < 4; j++) {          // 4 k8-chunks per BK=32
            uint32_t af[4][4], bf[8][2];
            #pragma unroll
            for (int mi = 0; mi < 4; mi++) {
                float2 x1 = *(const float2*)(as + rA[mi] + koff[j]);
                float2 x2 = *(const float2*)(as + rA[mi] + 256 + koff[j]);  // +8 rows
                af[mi][0] = __float_as_uint(x1.x);
                af[mi][2] = __float_as_uint(x1.y);
                af[mi][1] = __float_as_uint(x2.x);
                af[mi][3] = __float_as_uint(x2.y);
            }
            #pragma unroll
            for (int ni = 0; ni < 8; ni++) {
                float2 y = *(const float2*)(bs + rB[ni] + koff[j]);
                bf[ni][0] = __float_as_uint(y.x);
                bf[ni][1] = __float_as_uint(y.y);
            }
            #pragma unroll
            for (int mi = 0; mi < 4; mi++)
                #pragma unroll
                for (int ni = 0; ni < 8; ni++)
                    mma_tf32(acc[mi][ni], af[mi], bf[ni]);
        }
    }

    const bool dogelu  = (mode & 1) != 0;
    const bool doround = (mode & 2) != 0;
    const bool doperm  = (mode & 4) != 0;
    const int  p0 = (tig < 2) ? 4 * tig     : 4 * tig - 7;   // permuted pos of orig col 2t
    const int  p1 = (tig < 2) ? 4 * tig + 2 : 4 * tig - 5;   // permuted pos of orig col 2t+1
    #pragma unroll
    for (int ni = 0; ni < 8; ni++) {
        const int gb = n0 + nw + ni * 8;
        const int cc = gb + 2 * tig;
        const float bv0 = bias[cc], bv1 = bias[cc + 1];
        #pragma unroll
        for (int mi = 0; mi < 4; mi++) {
            const int r0 = m0 + mw + mi * 16 + g;
            float v00 = acc[mi][ni][0] + bv0;
            float v01 = acc[mi][ni][1] + bv1;
            float v10 = acc[mi][ni][2] + bv0;
            float v11 = acc[mi][ni][3] + bv1;
            if (dogelu) {
                v00 = 0.5f * v00 * (1.0f + erff(v00 * 0.70710678118654752f));
                v01 = 0.5f * v01 * (1.0f + erff(v01 * 0.70710678118654752f));
                v10 = 0.5f * v10 * (1.0f + erff(v10 * 0.70710678118654752f));
                v11 = 0.5f * v11 * (1.0f + erff(v11 * 0.70710678118654752f));
            }
            if (doround) {
                v00 = rtf(v00); v01 = rtf(v01); v10 = rtf(v10); v11 = rtf(v11);
            }
            if (doperm) {
                C[(size_t)r0 * N + gb + p0]       = v00;
                C[(size_t)r0 * N + gb + p1]       = v01;
                C[(size_t)(r0 + 8) * N + gb + p0] = v10;
                C[(size_t)(r0 + 8) * N + gb + p1] = v11;
            } else {
                *(float2*)(C + (size_t)r0 * N + cc)       = make_float2(v00, v01);
                *(float2*)(C + (size_t)(r0 + 8) * N + cc) = make_float2(v10, v11);
            }
        }
    }
}

// ================= tensor-core flash attention (qkv tf32-rounded, d-axis permuted) ==
#define QP 72   // pitch for Qs/Ks/Vs: conflict-free float2 frag loads over d
#define PP 68   // pitch for Ps: conflict-free scalar loads over s

__global__ __launch_bounds__(256, 2) void attn_mma_kernel(
    const float* __restrict__ qkv, float* __restrict__ ctx)
{
    __shared__ float Qs[128][QP];
    __shared__ float Ks[64][QP];
    __shared__ float Vs[64][QP];
    __shared__ float Ps[128][PP];

    const int bh = blockIdx.y;
    const int b = bh >> 4, h = bh & 15;
    const int q0 = blockIdx.x * 128;
    const int tid = threadIdx.x;
    const int warp = tid >> 5, lane = tid & 31;
    const int g = lane >> 2, t = lane & 3;
    const int mw = warp * 16;

    // stage Q (scaled by 1/8, exact)
    #pragma unroll
    for (int i = 0; i < 8; i++) {
        int idx = tid + i * 256;
        int row = idx >> 4, c4 = (idx & 15) * 4;
        float4 v = *(const float4*)(qkv + (size_t)(b*SEQ + q0 + row) * 3072 + h*DHEAD + c4);
        v.x *= 0.125f; v.y *= 0.125f; v.z *= 0.125f; v.w *= 0.125f;
        *(float4*)&Qs[row][c4] = v;
    }

    float o[8][4];
    #pragma unroll
    for (int nt = 0; nt < 8; nt++)
        #pragma unroll
        for (int r = 0; r < 4; r++) o[nt][r] = 0.0f;
    float m0 = -1e30f, m1 = -1e30f, l0 = 0.0f, l1 = 0.0f;

    for (int kb = 0; kb < SEQ; kb += 64) {
        __syncthreads();
        #pragma unroll
        for (int i = 0; i < 4; i++) {
            int idx = tid + i * 256;
            int row = idx >> 4, c4 = (idx & 15) * 4;
            const float* base = qkv + (size_t)(b*SEQ + kb + row) * 3072 + h*DHEAD + c4;
            *(float4*)&Ks[row][c4] = *(const float4*)(base + 1024);
            *(float4*)&Vs[row][c4] = *(const float4*)(base + 2048);
        }
        __syncthreads();

        // ---- S = Q @ K^T ----
        float sacc[8][4];
        #pragma unroll
        for (int nt = 0; nt < 8; nt++)
            #pragma unroll
            for (int r = 0; r < 4; r++) sacc[nt][r] = 0.0f;

        #pragma unroll
        for (int kt = 0; kt < 8; kt++) {
            uint32_t af[4];
            float2 q1 = *(const float2*)&Qs[mw + g][kt*8 + 2*t];
            float2 q2 = *(const float2*)&Qs[mw + g + 8][kt*8 + 2*t];
            af[0] = __float_as_uint(q1.x); af[2] = __float_as_uint(q1.y);
            af[1] = __float_as_uint(q2.x); af[3] = __float_as_uint(q2.y);
            #pragma unroll
            for (int nt = 0; nt < 8; nt++) {
                uint32_t bf[2];
                float2 kv = *(const float2*)&Ks[nt*8 + g][kt*8 + 2*t];
                bf[0] = __float_as_uint(kv.x); bf[1] = __float_as_uint(kv.y);
                mma_tf32(sacc[nt], af, bf);
            }
        }

        // ---- online softmax ----
        float rmax0 = -1e30f, rmax1 = -1e30f;
        #pragma unroll
        for (int nt = 0; nt < 8; nt++) {
            rmax0 = fmaxf(rmax0, fmaxf(sacc[nt][0], sacc[nt][1]));
            rmax1 = fmaxf(rmax1, fmaxf(sacc[nt][2], sacc[nt][3]));
        }
        #pragma unroll
        for (int d = 1; d < 4; d <<= 1) {
            rmax0 = fmaxf(rmax0, __shfl_xor_sync(0xffffffffu, rmax0, d));
            rmax1 = fmaxf(rmax1, __shfl_xor_sync(0xffffffffu, rmax1, d));
        }
        float m0n = fmaxf(m0, rmax0), m1n = fmaxf(m1, rmax1);
        float c0 = __expf(m0 - m0n), c1 = __expf(m1 - m1n);
        m0 = m0n; m1 = m1n;

        float sum0 = 0.0f, sum1 = 0.0f;
        #pragma unroll
        for (int nt = 0; nt < 8; nt++) {
            sacc[nt][0] = __expf(sacc[nt][0] - m0);
            sacc[nt][1] = __expf(sacc[nt][1] - m0);
            sacc[nt][2] = __expf(sacc[nt][2] - m1);
            sacc[nt][3] = __expf(sacc[nt][3] - m1);
            sum0 += sacc[nt][0] + sacc[nt][1];
            sum1 += sacc[nt][2] + sacc[nt][3];
        }
        #pragma unroll
        for (int d = 1; d < 4; d <<= 1) {
            sum0 += __shfl_xor_sync(0xffffffffu, sum0, d);
            sum1 += __shfl_xor_sync(0xffffffffu, sum1, d);
        }
        l0 = l0 * c0 + sum0;
        l1 = l1 * c1 + sum1;
        #pragma unroll
        for (int nt = 0; nt < 8; nt++) {
            o[nt][0] *= c0; o[nt][1] *= c0;
            o[nt][2] *= c1; o[nt][3] *= c1;
        }

        // write P (rounded once; s-axis unpermuted)
        #pragma unroll
        for (int nt = 0; nt < 8; nt++) {
            *(float2*)&Ps[mw + g][nt*8 + 2*t]     = make_float2(rtf(sacc[nt][0]), rtf(sacc[nt][1]));
            *(float2*)&Ps[mw + g + 8][nt*8 + 2*t] = make_float2(rtf(sacc[nt][2]), rtf(sacc[nt][3]));
        }
        __syncwarp();

        // ---- O += P @ V ----
        #pragma unroll
        for (int kt = 0; kt < 8; kt++) {
            uint32_t af[4];
            const float* p  = &Ps[mw + g][kt*8 + t];
            const float* p2 = p + 8 * PP;
            af[0] = __float_as_uint(p[0]);  af[2] = __float_as_uint(p[4]);
            af[1] = __float_as_uint(p2[0]); af[3] = __float_as_uint(p2[4]);
            #pragma unroll
            for (int nt = 0; nt < 8; nt++) {
                uint32_t bf[2];
                bf[0] = __float_as_uint(Vs[kt*8 + t][nt*8 + g]);
                bf[1] = __float_as_uint(Vs[kt*8 + t + 4][nt*8 + g]);
                mma_tf32(o[nt], af, bf);
            }
        }
    }

    float inv0 = 1.0f / l0, inv1 = 1.0f / l1;
    const int r0 = b*SEQ + q0 + mw + g;
    const int cbase = h*DHEAD + 2*t;
    #pragma unroll
    for (int nt = 0; nt < 8; nt++) {
        *(float2*)(ctx + (size_t)r0 * WID + cbase + nt*8) =
            make_float2(rtf(o[nt][0]*inv0), rtf(o[nt][1]*inv0));
        *(float2*)(ctx + (size_t)(r0 + 8) * WID + cbase + nt*8) =
            make_float2(rtf(o[nt][2]*inv1), rtf(o[nt][3]*inv1));
    }
}

// ---------------- residual add + LayerNorm (+ optional rounded PERMUTED copy) -------
__global__ __launch_bounds__(256) void add_ln_kernel(
    const float* __restrict__ resid, const float* __restrict__ x,
    const float* __restrict__ gg, const float* __restrict__ bb,
    float* __restrict__ out, float* __restrict__ outr)
{
    __shared__ float2 sm[8];
    const size_t row = blockIdx.x;
    const int tid = threadIdx.x;

    float4 r = *(const float4*)(resid + row*WID + tid*4);
    float4 v = *(const float4*)(x     + row*WID + tid*4);
    float4 tv;
    tv.x = r.x + v.x; tv.y = r.y + v.y; tv.z = r.z + v.z; tv.w = r.w + v.w;

    float s = tv.x + tv.y + tv.z + tv.w;
    float qq = tv.x*tv.x + tv.y*tv.y + tv.z*tv.z + tv.w*tv.w;

    int lane = tid & 31, warp = tid >> 5;
    #pragma unroll
    for (int o = 16; o > 0; o >>= 1) {
        s  += __shfl_down_sync(0xffffffffu, s,  o);
        qq += __shfl_down_sync(0xffffffffu, qq, o);
    }
    if (lane == 0) sm[warp] = make_float2(s, qq);
    __syncthreads();
    if (warp == 0) {
        float2 w2 = (lane < 8) ? sm[lane] : make_float2(0.f, 0.f);
        #pragma unroll
        for (int o = 4; o > 0; o >>= 1) {
            w2.x += __shfl_down_sync(0xffffffffu, w2.x, o);
            w2.y += __shfl_down_sync(0xffffffffu, w2.y, o);
        }
        if (lane == 0) sm[0] = w2;
    }
    __syncthreads();
    float mean = sm[0].x * (1.0f/WID);
    float var  = sm[0].y * (1.0f/WID) - mean*mean;
    float rstd = rsqrtf(var + 1e-5f);

    float4 g4 = *(const float4*)(gg + tid*4);
    float4 b4 = *(const float4*)(bb + tid*4);
    float4 o;
    o.x = (tv.x - mean)*rstd*g4.x + b4.x;
    o.y = (tv.y - mean)*rstd*g4.y + b4.y;
    o.z = (tv.z - mean)*rstd*g4.z + b4.z;
    o.w = (tv.w - mean)*rstd*g4.w + b4.w;
    *(float4*)(out + row*WID + tid*4) = o;
    if (outr) {
        // permuted scatter: group = tid>>1; even tid holds orig 0..3 -> pos 0,2,4,6
        float* d = outr + row*WID + (size_t)(tid >> 1) * 8 + (tid & 1);
        d[0] = rtf(o.x); d[2] = rtf(o.y); d[4] = rtf(o.z); d[6] = rtf(o.w);
    }
}

// ---------------- masked max-pool ----------------
__global__ __launch_bounds__(256) void maxpool_kernel(
    const float* __restrict__ hidden, const int* __restrict__ in_ids,
    const int* __restrict__ resp_ids, float* __restrict__ mp)
{
    const int g = blockIdx.x;
    const int b = blockIdx.y;
    const int tid = threadIdx.x;
    __shared__ unsigned char flag[SEQ];

    for (int s = tid; s < SEQ; s += 256) {
        bool f = false;
        if (g < 6) { if (s < SIN) f = (in_ids[b*SIN + s] == g + 1); }
        else       { if (s >= SIN) f = (resp_ids[b*SRES + (s - SIN + 1)] == 1); }
        flag[s] = f ? 1 : 0;
    }
    __syncthreads();

    const int w = tid * 4;
    float4 vm = make_float4(0.f, 0.f, 0.f, 0.f);
    for (int s = 0; s < SEQ; s++) {
        if (flag[s]) {
            float4 hv = *(const float4*)(hidden + (size_t)(b*SEQ + s)*WID + w);
            vm.x = fmaxf(vm.x, hv.x); vm.y = fmaxf(vm.y, hv.y);
            vm.z = fmaxf(vm.z, hv.z); vm.w = fmaxf(vm.w, hv.w);
        }
    }
    *(float4*)(mp + (size_t)(g*BATCH + b)*WID + w) = vm;
}

// ---------------- topic softmax + gather ----------------
__global__ __launch_bounds__(256) void topic_kernel(
    const float* __restrict__ mp, const float* __restrict__ tw,
    const float* __restrict__ tb, const float* __restrict__ table,
    float* __restrict__ ue)
{
    const int gb = blockIdx.x;
    const int tid = threadIdx.x;
    __shared__ float mpv[WID];
    __shared__ float probs[NTOP];
    __shared__ float logits[NTOP];

    *(float4*)&mpv[tid*4] = *(const float4*)(mp + (size_t)gb*WID + tid*4);
    __syncthreads();

    const int warp = tid >> 5, lane = tid & 31;
    for (int t = warp; t < NTOP; t += 8) {
        const float* wr = tw + (size_t)t * WID;
        float s = 0.0f;
        for (int w = lane; w < WID; w += 32) s = fmaf(mpv[w], wr[w], s);
        #pragma unroll
        for (int o = 16; o > 0; o >>= 1) s += __shfl_down_sync(0xffffffffu, s, o);
        if (lane == 0) logits[t] = s + tb[t];
    }
    __syncthreads();

    if (tid == 0) {
        float m = -1e30f;
        for (int t = 0; t < NTOP; t++) m = fmaxf(m, logits[t]);
        float sum = 0.0f;
        for (int t = 0; t < NTOP; t++) { float e = expf(logits[t] - m); probs[t] = e; sum += e; }
        float inv = 1.0f / sum;
        for (int t = 0; t < NTOP; t++) probs[t] *= inv;
    }
    __syncthreads();

    const int w = tid * 4;
    float4 a = make_float4(0.f, 0.f, 0.f, 0.f);
    for (int t = 0; t < NTOP; t++) {
        float p = probs[t];
        float4 tv = *(const float4*)(table + (size_t)t*WID + w);
        a.x = fmaf(p, tv.x, a.x); a.y = fmaf(p, tv.y, a.y);
        a.z = fmaf(p, tv.z, a.z); a.w = fmaf(p, tv.w, a.w);
    }
    *(float4*)(ue + (size_t)gb*WID + w) = a;
}

// ---------------- final output ----------------
__global__ __launch_bounds__(256) void out_kernel(
    const float* __restrict__ X, const int* __restrict__ in_ids,
    const int* __restrict__ resp_ids, const float* __restrict__ ue,
    float* __restrict__ out)
{
    const int bs = blockIdx.x;
    const int b = bs >> 9, s = bs & 511;
    int g = -1; float c = 0.0f;
    if (s < SIN) {
        int v = in_ids[b*SIN + s];
        if (v > 0)      { g = v - 1;   c = 1.0f; }
        else if (v < 0) { g = -v - 1;  c = 2.0f; }
    } else {
        int v = resp_ids[b*SRES + (s - SIN + 1)];
        if (v == 1)       { g = 6; c = 1.0f; }
        else if (v == -1) { g = 6; c = 2.0f; }
    }
    const int w = threadIdx.x * 4;
    float4 xv = *(const float4*)(X + (size_t)bs*WID + w);
    if (g >= 0) {
        float4 u = *(const float4*)(ue + (size_t)(g*BATCH + b)*WID + w);
        xv.x = fmaf(c, u.x, xv.x); xv.y = fmaf(c, u.y, xv.y);
        xv.z = fmaf(c, u.z, xv.z); xv.w = fmaf(c, u.w, xv.w);
    }
    *(float4*)(out + (size_t)bs*WID + w) = xv;
}

// ---------------- launch ----------------
extern "C" void kernel_launch(void* const* d_in, const int* in_sizes, int n_in,
                              void* d_out, int out_size)
{
    const float* X       = (const float*)d_in[0];
    const int*   in_ids  = (const int*)  d_in[1];
    const int*   resp_ids= (const int*)  d_in[2];
    const float* Wqkv    = (const float*)d_in[3];
    const float* bqkv    = (const float*)d_in[4];
    const float* Wo      = (const float*)d_in[5];
    const float* bo      = (const float*)d_in[6];
    const float* ln1g    = (const float*)d_in[7];
    const float* ln1b    = (const float*)d_in[8];
    const float* W1      = (const float*)d_in[9];
    const float* b1      = (const float*)d_in[10];
    const float* W2      = (const float*)d_in[11];
    const float* b2      = (const float*)d_in[12];
    const float* ln2g    = (const float*)d_in[13];
    const float* ln2b    = (const float*)d_in[14];
    const float* tw      = (const float*)d_in[15];
    const float* tb      = (const float*)d_in[16];
    const float* table   = (const float*)d_in[17];
    float* out = (float*)d_out;

    float *qkv, *ctx, *tmp, *y, *hid, *wr, *mp, *ue;
    cudaGetSymbolAddress((void**)&qkv, g_qkv);
    cudaGetSymbolAddress((void**)&ctx, g_ctx);
    cudaGetSymbolAddress((void**)&tmp, g_tmp);
    cudaGetSymbolAddress((void**)&y,   g_y);
    cudaGetSymbolAddress((void**)&hid, g_hid);
    cudaGetSymbolAddress((void**)&wr,  g_wr);
    cudaGetSymbolAddress((void**)&mp,  g_mp);
    cudaGetSymbolAddress((void**)&ue,  g_ue);

    float* wqkv_r = wr;                 // 3,145,728
    float* wo_r   = wr + 3145728;       // 1,048,576
    float* w1_r   = wr + 4194304;       // 4,194,304
    float* w2_r   = wr + 8388608;       // 4,194,304
    float* xr     = hid;                // rounded+permuted X (hid free until step 7)

    const int smem = NSTAGE * STAGE_F * 2 * sizeof(float);   // 98,304 B
    cudaFuncSetAttribute(mma_gemm, cudaFuncAttributeMaxDynamicSharedMemorySize, smem);

    // 0. round+permute X and all weights (counts in float8 units)
    round_perm_multi<<<8192, 256>>>(
        X,    xr,     (MROWS*WID)/8,
        Wqkv, wqkv_r, (3072*1024)/8,
        Wo,   wo_r,   (1024*1024)/8,
        W1,   w1_r,   (4096*1024)/8,
        W2,   w2_r,   (1024*4096)/8);

    // 1. QKV (round + permute output cols -> attention reads permuted d)
    mma_gemm<<<dim3(3072/BN, MROWS/BM), 128, smem>>>(xr, wqkv_r, bqkv, qkv, MROWS, 3072, 1024, 6);
    // 2. attention (ctx cols inherit permuted d-labels, rounded)
    attn_mma_kernel<<<dim3(SEQ/128, BATCH*HEADS), 256>>>(qkv, ctx);
    // 3. proj
    mma_gemm<<<dim3(WID/BN, MROWS/BM), 128, smem>>>(ctx, wo_r, bo, tmp, MROWS, WID, 1024, 0);
    // 4. y = LN(X + proj), plus rounded+permuted copy into ctx
    add_ln_kernel<<<MROWS, 256>>>(X, tmp, ln1g, ln1b, y, ctx);
    // 5. FF1 + GELU (round + permute -> FF2)
    mma_gemm<<<dim3(DFF/BN, MROWS/BM), 128, smem>>>(ctx, w1_r, b1, tmp, MROWS, DFF, 1024, 7);
    // 6. FF2
    mma_gemm<<<dim3(WID/BN, MROWS/BM), 128, smem>>>(tmp, w2_r, b2, ctx, MROWS, WID, 4096, 0);
    // 7. hidden = LN(y + FF2)
    add_ln_kernel<<<MROWS, 256>>>(y, ctx, ln2g, ln2b, hid, nullptr);
    // 8-10. topic path + final output
    maxpool_kernel<<<dim3(NGRP, BATCH), 256>>>(hid, in_ids, resp_ids, mp);
    topic_kernel<<<NGRP*BATCH, 256>>>(mp, tw, tb, table, ue);
    out_kernel<<<MROWS, 256>>>(X, in_ids, resp_ids, ue, out);
}

// round 16
// speedup vs baseline: 4.3488x; 1.0274x over previous
#include <cuda_runtime.h>
#include <math.h>
#include <cstdint>

// ---------------- problem constants ----------------
#define BATCH 16
#define SEQ   512
#define SIN   384
#define SRES  129
#define WID   1024
#define HEADS 16
#define DHEAD 64
#define DFF   4096
#define NTOP  50
#define NGRP  7
#define MROWS (BATCH*SEQ)   // 8192

// ---------------- scratch ----------------
__device__ float g_qkv[(size_t)MROWS * 3072];
__device__ float g_ctx[(size_t)MROWS * WID];
__device__ float g_tmp[(size_t)MROWS * DFF];
__device__ float g_y  [(size_t)MROWS * WID];
__device__ float g_hid[(size_t)MROWS * WID];      // rounded+permuted X early, hidden late
__device__ float g_wr [12582912];                  // rounded+permuted weights
__device__ float g_mp [NGRP * BATCH * WID];
__device__ float g_ue [NGRP * BATCH * WID];

// round-to-nearest tf32
__device__ __forceinline__ uint32_t f2tf(float x) {
    uint32_t r;
    asm("cvt.rna.tf32.f32 %0, %1;" : "=r"(r) : "f"(x));
    return r;
}
__device__ __forceinline__ float rtf(float x) { return __uint_as_float(f2tf(x)); }

__device__ __forceinline__ void mma_tf32(float* c, const uint32_t* a, const uint32_t* b) {
    asm volatile(
        "mma.sync.aligned.m16n8k8.row.col.f32.tf32.tf32.f32 "
        "{%0,%1,%2,%3}, {%4,%5,%6,%7}, {%8,%9}, {%0,%1,%2,%3};"
        : "+f"(c[0]), "+f"(c[1]), "+f"(c[2]), "+f"(c[3])
        : "r"(a[0]), "r"(a[1]), "r"(a[2]), "r"(a[3]), "r"(b[0]), "r"(b[1]));
}

__device__ __forceinline__ void cpa16(void* dst, const float* src) {
    uint32_t d = (uint32_t)__cvta_generic_to_shared(dst);
    asm volatile("cp.async.cg.shared.global [%0], [%1], 16;" :: "r"(d), "l"(src));
}

// ---------------- fused multi-tensor tf32 round + K-group permute ----------------
// permutation per 8-group: stored[2j] = orig[j], stored[2j+1] = orig[j+4]
__global__ __launch_bounds__(256) void round_perm_multi(
    const float* s0, float* d0, int n0,
    const float* s1, float* d1, int n1,
    const float* s2, float* d2, int n2,
    const float* s3, float* d3, int n3,
    const float* s4, float* d4, int n4)   // counts in float8 units
{
    int total = n0 + n1 + n2 + n3 + n4;
    for (int idx = blockIdx.x * 256 + threadIdx.x; idx < total; idx += gridDim.x * 256) {
        int i = idx;
        const float* s; float* d;
        if (i < n0) { s = s0; d = d0; }
        else { i -= n0;
            if (i < n1) { s = s1; d = d1; }
            else { i -= n1;
                if (i < n2) { s = s2; d = d2; }
                else { i -= n2;
                    if (i < n3) { s = s3; d = d3; }
                    else { i -= n3; s = s4; d = d4; } } } }
        float4 lo = *(const float4*)(s + (size_t)i * 8);
        float4 hi = *(const float4*)(s + (size_t)i * 8 + 4);
        float4 w0, w1;
        w0.x = rtf(lo.x); w0.y = rtf(hi.x); w0.z = rtf(lo.y); w0.w = rtf(hi.y);
        w1.x = rtf(lo.z); w1.y = rtf(hi.z); w1.z = rtf(lo.w); w1.w = rtf(hi.w);
        *(float4*)(d + (size_t)i * 8)     = w0;
        *(float4*)(d + (size_t)i * 8 + 4) = w1;
    }
}

// ================= TF32 tensor-core GEMM (permuted-K operands) =================
// (unchanged from R15 — proven config: 128 thr, warp tile 64x64, 1 sync/K-iter)
#define BM 128
#define BN 128
#define BK 32
#define NSTAGE 3
#define STAGE_F (BM * BK)    // 4096 floats per operand per stage

__global__ __launch_bounds__(128, 2) void mma_gemm(
    const float* __restrict__ A, const float* __restrict__ Bw,
    const float* __restrict__ bias, float* __restrict__ C,
    int M, int N, int K, int mode)
{
    extern __shared__ float smbuf[];
    float* As = smbuf;
    float* Bs = smbuf + NSTAGE * STAGE_F;

    const int tid  = threadIdx.x;
    const int m0   = blockIdx.y * BM;
    const int n0   = blockIdx.x * BN;
    const int warp = tid >> 5, lane = tid & 31;
    const int g    = lane >> 2, tig = lane & 3;
    const int mw   = (warp >> 1) * 64;   // 0 or 64
    const int nw   = (warp & 1) * 64;    // 0 or 64

    float acc[4][8][4];
    #pragma unroll
    for (int mi = 0; mi < 4; mi++)
        #pragma unroll
        for (int ni = 0; ni < 8; ni++)
            #pragma unroll
            for (int r = 0; r < 4; r++) acc[mi][ni][r] = 0.0f;

    const int kiters = K / BK;

    const int swz = (g & 3) << 1;
    const int t2  = tig >> 1;
    const int tl  = (tig & 1) << 1;
    int koff[4];
    #pragma unroll
    for (int j = 0; j < 4; j++) koff[j] = (((j << 1) ^ swz) << 2);
    int rA[4], rB[8];
    #pragma unroll
    for (int mi = 0; mi < 4; mi++) rA[mi] = (mw + mi * 16 + g) * 32 + 4 * t2 + tl;
    #pragma unroll
    for (int ni = 0; ni < 8; ni++) rB[ni] = (nw + ni * 8 + g) * 32 + 4 * t2 + tl;

    #pragma unroll
    for (int s = 0; s < NSTAGE - 1; s++) {
        const int k0 = s * BK;
        #pragma unroll
        for (int i = 0; i < 8; i++) {
            int c = tid + (i << 7);
            int row = c >> 3, ch = c & 7;
            int dst = row * 32 + ((ch ^ ((row & 3) << 1)) << 2);
            cpa16(As + s * STAGE_F + dst, A  + (size_t)(m0 + row) * K + k0 + ch * 4);
            cpa16(Bs + s * STAGE_F + dst, Bw + (size_t)(n0 + row) * K + k0 + ch * 4);
        }
        asm volatile("cp.async.commit_group;");
    }

    for (int kt = 0; kt < kiters; kt++) {
        asm volatile("cp.async.wait_group %0;" :: "n"(NSTAGE - 2));
        __syncthreads();

        const int ps = kt + NSTAGE - 1;
        if (ps < kiters) {
            const int s = ps % NSTAGE;
            const int k0 = ps * BK;
            #pragma unroll
            for (int i = 0; i < 8; i++) {
                int c = tid + (i << 7);
                int row = c >> 3, ch = c & 7;
                int dst = row * 32 + ((ch ^ ((row & 3) << 1)) << 2);
                cpa16(As + s * STAGE_F + dst, A  + (size_t)(m0 + row) * K + k0 + ch * 4);
                cpa16(Bs + s * STAGE_F + dst, Bw + (size_t)(n0 + row) * K + k0 + ch * 4);
            }
        }
        asm volatile("cp.async.commit_group;");   // always (empty in tail)

        const float* as = As + (kt % NSTAGE) * STAGE_F;
        const float* bs = Bs + (kt % NSTAGE) * STAGE_F;

        #pragma unroll
        for (int j = 0; j < 4; j++) {
            uint32_t af[4][4], bf[8][2];
            #pragma unroll
            for (int mi = 0; mi < 4; mi++) {
                float2 x1 = *(const float2*)(as + rA[mi] + koff[j]);
                float2 x2 = *(const float2*)(as + rA[mi] + 256 + koff[j]);
                af[mi][0] = __float_as_uint(x1.x);
                af[mi][2] = __float_as_uint(x1.y);
                af[mi][1] = __float_as_uint(x2.x);
                af[mi][3] = __float_as_uint(x2.y);
            }
            #pragma unroll
            for (int ni = 0; ni < 8; ni++) {
                float2 y = *(const float2*)(bs + rB[ni] + koff[j]);
                bf[ni][0] = __float_as_uint(y.x);
                bf[ni][1] = __float_as_uint(y.y);
            }
            #pragma unroll
            for (int mi = 0; mi < 4; mi++)
                #pragma unroll
                for (int ni = 0; ni < 8; ni++)
                    mma_tf32(acc[mi][ni], af[mi], bf[ni]);
        }
    }

    const bool dogelu  = (mode & 1) != 0;
    const bool doround = (mode & 2) != 0;
    const bool doperm  = (mode & 4) != 0;
    const int  p0 = (tig < 2) ? 4 * tig     : 4 * tig - 7;
    const int  p1 = (tig < 2) ? 4 * tig + 2 : 4 * tig - 5;
    #pragma unroll
    for (int ni = 0; ni < 8; ni++) {
        const int gb = n0 + nw + ni * 8;
        const int cc = gb + 2 * tig;
        const float bv0 = bias[cc], bv1 = bias[cc + 1];
        #pragma unroll
        for (int mi = 0; mi < 4; mi++) {
            const int r0 = m0 + mw + mi * 16 + g;
            float v00 = acc[mi][ni][0] + bv0;
            float v01 = acc[mi][ni][1] + bv1;
            float v10 = acc[mi][ni][2] + bv0;
            float v11 = acc[mi][ni][3] + bv1;
            if (dogelu) {
                v00 = 0.5f * v00 * (1.0f + erff(v00 * 0.70710678118654752f));
                v01 = 0.5f * v01 * (1.0f + erff(v01 * 0.70710678118654752f));
                v10 = 0.5f * v10 * (1.0f + erff(v10 * 0.70710678118654752f));
                v11 = 0.5f * v11 * (1.0f + erff(v11 * 0.70710678118654752f));
            }
            if (doround) {
                v00 = rtf(v00); v01 = rtf(v01); v10 = rtf(v10); v11 = rtf(v11);
            }
            if (doperm) {
                C[(size_t)r0 * N + gb + p0]       = v00;
                C[(size_t)r0 * N + gb + p1]       = v01;
                C[(size_t)(r0 + 8) * N + gb + p0] = v10;
                C[(size_t)(r0 + 8) * N + gb + p1] = v11;
            } else {
                *(float2*)(C + (size_t)r0 * N + cc)       = make_float2(v00, v01);
                *(float2*)(C + (size_t)(r0 + 8) * N + cc) = make_float2(v10, v11);
            }
        }
    }
}

// ================= tensor-core flash attention (tf32, d-axis permuted) =============
// cp.async double-buffered K/V; P relayed register-to-register via quad shuffles
// (C-frag cols 2t/2t+1 -> A-frag cols t/t+4). Bit-exact vs the smem-Ps version.
#define QP 72   // pitch: conflict-free float2 frag loads over d

__global__ __launch_bounds__(256, 2) void attn_mma_kernel(
    const float* __restrict__ qkv, float* __restrict__ ctx)
{
    __shared__ float Qs[128][QP];
    __shared__ float Ks[2][64][QP];
    __shared__ float Vs[2][64][QP];

    const int bh = blockIdx.y;
    const int b = bh >> 4, h = bh & 15;
    const int q0 = blockIdx.x * 128;
    const int tid = threadIdx.x;
    const int warp = tid >> 5, lane = tid & 31;
    const int g = lane >> 2, t = lane & 3;
    const int mw = warp * 16;

    // stage Q (scaled by 1/8, exact)
    #pragma unroll
    for (int i = 0; i < 8; i++) {
        int idx = tid + i * 256;
        int row = idx >> 4, c4 = (idx & 15) * 4;
        float4 v = *(const float4*)(qkv + (size_t)(b*SEQ + q0 + row) * 3072 + h*DHEAD + c4);
        v.x *= 0.125f; v.y *= 0.125f; v.z *= 0.125f; v.w *= 0.125f;
        *(float4*)&Qs[row][c4] = v;
    }

    // async K/V staging: 64 rows x 16 chunks(16B) per operand, 4 chunk-pairs/thread
    auto stage_kv = [&](int kb, int buf) {
        #pragma unroll
        for (int i = 0; i < 4; i++) {
            int c = tid + (i << 8);
            int row = c >> 4, ch = c & 15;
            const float* base = qkv + (size_t)(b*SEQ + kb + row) * 3072 + h*DHEAD + ch * 4;
            cpa16(&Ks[buf][row][ch * 4], base + 1024);
            cpa16(&Vs[buf][row][ch * 4], base + 2048);
        }
    };

    float o[8][4];
    #pragma unroll
    for (int nt = 0; nt < 8; nt++)
        #pragma unroll
        for (int r = 0; r < 4; r++) o[nt][r] = 0.0f;
    float m0 = -1e30f, m1 = -1e30f, l0 = 0.0f, l1 = 0.0f;

    stage_kv(0, 0);
    asm volatile("cp.async.commit_group;");

    for (int it = 0; it < 8; it++) {
        const int cur = it & 1;
        if (it < 7) stage_kv((it + 1) * 64, (it + 1) & 1);
        asm volatile("cp.async.commit_group;");   // always (empty in tail)
        asm volatile("cp.async.wait_group 1;");   // buffer `cur` complete
        __syncthreads();

        // ---- S = Q @ K^T ----
        float sacc[8][4];
        #pragma unroll
        for (int nt = 0; nt < 8; nt++)
            #pragma unroll
            for (int r = 0; r < 4; r++) sacc[nt][r] = 0.0f;

        #pragma unroll
        for (int kt = 0; kt < 8; kt++) {
            uint32_t af[4];
            float2 q1 = *(const float2*)&Qs[mw + g][kt*8 + 2*t];
            float2 q2 = *(const float2*)&Qs[mw + g + 8][kt*8 + 2*t];
            af[0] = __float_as_uint(q1.x); af[2] = __float_as_uint(q1.y);
            af[1] = __float_as_uint(q2.x); af[3] = __float_as_uint(q2.y);
            #pragma unroll
            for (int nt = 0; nt < 8; nt++) {
                uint32_t bf[2];
                float2 kv = *(const float2*)&Ks[cur][nt*8 + g][kt*8 + 2*t];
                bf[0] = __float_as_uint(kv.x); bf[1] = __float_as_uint(kv.y);
                mma_tf32(sacc[nt], af, bf);
            }
        }

        // ---- online softmax ----
        float rmax0 = -1e30f, rmax1 = -1e30f;
        #pragma unroll
        for (int nt = 0; nt < 8; nt++) {
            rmax0 = fmaxf(rmax0, fmaxf(sacc[nt][0], sacc[nt][1]));
            rmax1 = fmaxf(rmax1, fmaxf(sacc[nt][2], sacc[nt][3]));
        }
        #pragma unroll
        for (int d = 1; d < 4; d <<= 1) {
            rmax0 = fmaxf(rmax0, __shfl_xor_sync(0xffffffffu, rmax0, d));
            rmax1 = fmaxf(rmax1, __shfl_xor_sync(0xffffffffu, rmax1, d));
        }
        float m0n = fmaxf(m0, rmax0), m1n = fmaxf(m1, rmax1);
        float c0 = __expf(m0 - m0n), c1 = __expf(m1 - m1n);
        m0 = m0n; m1 = m1n;

        float sum0 = 0.0f, sum1 = 0.0f;
        #pragma unroll
        for (int nt = 0; nt < 8; nt++) {
            sacc[nt][0] = __expf(sacc[nt][0] - m0);
            sacc[nt][1] = __expf(sacc[nt][1] - m0);
            sacc[nt][2] = __expf(sacc[nt][2] - m1);
            sacc[nt][3] = __expf(sacc[nt][3] - m1);
            sum0 += sacc[nt][0] + sacc[nt][1];
            sum1 += sacc[nt][2] + sacc[nt][3];
        }
        #pragma unroll
        for (int d = 1; d < 4; d <<= 1) {
            sum0 += __shfl_xor_sync(0xffffffffu, sum0, d);
            sum1 += __shfl_xor_sync(0xffffffffu, sum1, d);
        }
        l0 = l0 * c0 + sum0;
        l1 = l1 * c1 + sum1;
        #pragma unroll
        for (int nt = 0; nt < 8; nt++) {
            o[nt][0] *= c0; o[nt][1] *= c0;
            o[nt][2] *= c1; o[nt][3] *= c1;
        }

        // round P in-registers (same rounding point as the old smem path)
        #pragma unroll
        for (int nt = 0; nt < 8; nt++) {
            sacc[nt][0] = rtf(sacc[nt][0]);
            sacc[nt][1] = rtf(sacc[nt][1]);
            sacc[nt][2] = rtf(sacc[nt][2]);
            sacc[nt][3] = rtf(sacc[nt][3]);
        }

        // ---- O += P @ V : A-frags via quad shuffles ----
        const int L1 = (lane & 28) | (t >> 1);
        #pragma unroll
        for (int kt = 0; kt < 8; kt++) {
            float s0a = __shfl_sync(0xffffffffu, sacc[kt][0], L1);
            float s1a = __shfl_sync(0xffffffffu, sacc[kt][1], L1);
            float s2a = __shfl_sync(0xffffffffu, sacc[kt][2], L1);
            float s3a = __shfl_sync(0xffffffffu, sacc[kt][3], L1);
            float s0b = __shfl_sync(0xffffffffu, sacc[kt][0], L1 + 2);
            float s1b = __shfl_sync(0xffffffffu, sacc[kt][1], L1 + 2);
            float s2b = __shfl_sync(0xffffffffu, sacc[kt][2], L1 + 2);
            float s3b = __shfl_sync(0xffffffffu, sacc[kt][3], L1 + 2);
            uint32_t af[4];
            af[0] = __float_as_uint((t & 1) ? s1a : s0a);   // row g,   col t
            af[1] = __float_as_uint((t & 1) ? s3a : s2a);   // row g+8, col t
            af[2] = __float_as_uint((t & 1) ? s1b : s0b);   // row g,   col t+4
            af[3] = __float_as_uint((t & 1) ? s3b : s2b);   // row g+8, col t+4
            #pragma unroll
            for (int nt = 0; nt < 8; nt++) {
                uint32_t bf[2];
                bf[0] = __float_as_uint(Vs[cur][kt*8 + t][nt*8 + g]);
                bf[1] = __float_as_uint(Vs[cur][kt*8 + t + 4][nt*8 + g]);
                mma_tf32(o[nt], af, bf);
            }
        }
        __syncthreads();   // protect buffer `cur` before it is refilled at it+1
    }

    float inv0 = 1.0f / l0, inv1 = 1.0f / l1;
    const int r0 = b*SEQ + q0 + mw + g;
    const int cbase = h*DHEAD + 2*t;
    #pragma unroll
    for (int nt = 0; nt < 8; nt++) {
        *(float2*)(ctx + (size_t)r0 * WID + cbase + nt*8) =
            make_float2(rtf(o[nt][0]*inv0), rtf(o[nt][1]*inv0));
        *(float2*)(ctx + (size_t)(r0 + 8) * WID + cbase + nt*8) =
            make_float2(rtf(o[nt][2]*inv1), rtf(o[nt][3]*inv1));
    }
}

// ---------------- residual add + LayerNorm (+ optional rounded PERMUTED copy) -------
__global__ __launch_bounds__(256) void add_ln_kernel(
    const float* __restrict__ resid, const float* __restrict__ x,
    const float* __restrict__ gg, const float* __restrict__ bb,
    float* __restrict__ out, float* __restrict__ outr)
{
    __shared__ float2 sm[8];
    const size_t row = blockIdx.x;
    const int tid = threadIdx.x;

    float4 r = *(const float4*)(resid + row*WID + tid*4);
    float4 v = *(const float4*)(x     + row*WID + tid*4);
    float4 tv;
    tv.x = r.x + v.x; tv.y = r.y + v.y; tv.z = r.z + v.z; tv.w = r.w + v.w;

    float s = tv.x + tv.y + tv.z + tv.w;
    float qq = tv.x*tv.x + tv.y*tv.y + tv.z*tv.z + tv.w*tv.w;

    int lane = tid & 31, warp = tid >> 5;
    #pragma unroll
    for (int o = 16; o > 0; o >>= 1) {
        s  += __shfl_down_sync(0xffffffffu, s,  o);
        qq += __shfl_down_sync(0xffffffffu, qq, o);
    }
    if (lane == 0) sm[warp] = make_float2(s, qq);
    __syncthreads();
    if (warp == 0) {
        float2 w2 = (lane < 8) ? sm[lane] : make_float2(0.f, 0.f);
        #pragma unroll
        for (int o = 4; o > 0; o >>= 1) {
            w2.x += __shfl_down_sync(0xffffffffu, w2.x, o);
            w2.y += __shfl_down_sync(0xffffffffu, w2.y, o);
        }
        if (lane == 0) sm[0] = w2;
    }
    __syncthreads();
    float mean = sm[0].x * (1.0f/WID);
    float var  = sm[0].y * (1.0f/WID) - mean*mean;
    float rstd = rsqrtf(var + 1e-5f);

    float4 g4 = *(const float4*)(gg + tid*4);
    float4 b4 = *(const float4*)(bb + tid*4);
    float4 o;
    o.x = (tv.x - mean)*rstd*g4.x + b4.x;
    o.y = (tv.y - mean)*rstd*g4.y + b4.y;
    o.z = (tv.z - mean)*rstd*g4.z + b4.z;
    o.w = (tv.w - mean)*rstd*g4.w + b4.w;
    *(float4*)(out + row*WID + tid*4) = o;
    if (outr) {
        float* d = outr + row*WID + (size_t)(tid >> 1) * 8 + (tid & 1);
        d[0] = rtf(o.x); d[2] = rtf(o.y); d[4] = rtf(o.z); d[6] = rtf(o.w);
    }
}

// ---------------- masked max-pool ----------------
__global__ __launch_bounds__(256) void maxpool_kernel(
    const float* __restrict__ hidden, const int* __restrict__ in_ids,
    const int* __restrict__ resp_ids, float* __restrict__ mp)
{
    const int g = blockIdx.x;
    const int b = blockIdx.y;
    const int tid = threadIdx.x;
    __shared__ unsigned char flag[SEQ];

    for (int s = tid; s < SEQ; s += 256) {
        bool f = false;
        if (g < 6) { if (s < SIN) f = (in_ids[b*SIN + s] == g + 1); }
        else       { if (s >= SIN) f = (resp_ids[b*SRES + (s - SIN + 1)] == 1); }
        flag[s] = f ? 1 : 0;
    }
    __syncthreads();

    const int w = tid * 4;
    float4 vm = make_float4(0.f, 0.f, 0.f, 0.f);
    for (int s = 0; s < SEQ; s++) {
        if (flag[s]) {
            float4 hv = *(const float4*)(hidden + (size_t)(b*SEQ + s)*WID + w);
            vm.x = fmaxf(vm.x, hv.x); vm.y = fmaxf(vm.y, hv.y);
            vm.z = fmaxf(vm.z, hv.z); vm.w = fmaxf(vm.w, hv.w);
        }
    }
    *(float4*)(mp + (size_t)(g*BATCH + b)*WID + w) = vm;
}

// ---------------- topic softmax + gather ----------------
__global__ __launch_bounds__(256) void topic_kernel(
    const float* __restrict__ mp, const float* __restrict__ tw,
    const float* __restrict__ tb, const float* __restrict__ table,
    float* __restrict__ ue)
{
    const int gb = blockIdx.x;
    const int tid = threadIdx.x;
    __shared__ float mpv[WID];
    __shared__ float probs[NTOP];
    __shared__ float logits[NTOP];

    *(float4*)&mpv[tid*4] = *(const float4*)(mp + (size_t)gb*WID + tid*4);
    __syncthreads();

    const int warp = tid >> 5, lane = tid & 31;
    for (int t = warp; t < NTOP; t += 8) {
        const float* wr = tw + (size_t)t * WID;
        float s = 0.0f;
        for (int w = lane; w < WID; w += 32) s = fmaf(mpv[w], wr[w], s);
        #pragma unroll
        for (int o = 16; o > 0; o >>= 1) s += __shfl_down_sync(0xffffffffu, s, o);
        if (lane == 0) logits[t] = s + tb[t];
    }
    __syncthreads();

    if (tid == 0) {
        float m = -1e30f;
        for (int t = 0; t < NTOP; t++) m = fmaxf(m, logits[t]);
        float sum = 0.0f;
        for (int t = 0; t < NTOP; t++) { float e = expf(logits[t] - m); probs[t] = e; sum += e; }
        float inv = 1.0f / sum;
        for (int t = 0; t < NTOP; t++) probs[t] *= inv;
    }
    __syncthreads();

    const int w = tid * 4;
    float4 a = make_float4(0.f, 0.f, 0.f, 0.f);
    for (int t = 0; t < NTOP; t++) {
        float p = probs[t];
        float4 tv = *(const float4*)(table + (size_t)t*WID + w);
        a.x = fmaf(p, tv.x, a.x); a.y = fmaf(p, tv.y, a.y);
        a.z = fmaf(p, tv.z, a.z); a.w = fmaf(p, tv.w, a.w);
    }
    *(float4*)(ue + (size_t)gb*WID + w) = a;
}

// ---------------- final output ----------------
__global__ __launch_bounds__(256) void out_kernel(
    const float* __restrict__ X, const int* __restrict__ in_ids,
    const int* __restrict__ resp_ids, const float* __restrict__ ue,
    float* __restrict__ out)
{
    const int bs = blockIdx.x;
    const int b = bs >> 9, s = bs & 511;
    int g = -1; float c = 0.0f;
    if (s < SIN) {
        int v = in_ids[b*SIN + s];
        if (v > 0)      { g = v - 1;   c = 1.0f; }
        else if (v < 0) { g = -v - 1;  c = 2.0f; }
    } else {
        int v = resp_ids[b*SRES + (s - SIN + 1)];
        if (v == 1)       { g = 6; c = 1.0f; }
        else if (v == -1) { g = 6; c = 2.0f; }
    }
    const int w = threadIdx.x * 4;
    float4 xv = *(const float4*)(X + (size_t)bs*WID + w);
    if (g >= 0) {
        float4 u = *(const float4*)(ue + (size_t)(g*BATCH + b)*WID + w);
        xv.x = fmaf(c, u.x, xv.x); xv.y = fmaf(c, u.y, xv.y);
        xv.z = fmaf(c, u.z, xv.z); xv.w = fmaf(c, u.w, xv.w);
    }
    *(float4*)(out + (size_t)bs*WID + w) = xv;
}

// ---------------- launch ----------------
extern "C" void kernel_launch(void* const* d_in, const int* in_sizes, int n_in,
                              void* d_out, int out_size)
{
    const float* X       = (const float*)d_in[0];
    const int*   in_ids  = (const int*)  d_in[1];
    const int*   resp_ids= (const int*)  d_in[2];
    const float* Wqkv    = (const float*)d_in[3];
    const float* bqkv    = (const float*)d_in[4];
    const float* Wo      = (const float*)d_in[5];
    const float* bo      = (const float*)d_in[6];
    const float* ln1g    = (const float*)d_in[7];
    const float* ln1b    = (const float*)d_in[8];
    const float* W1      = (const float*)d_in[9];
    const float* b1      = (const float*)d_in[10];
    const float* W2      = (const float*)d_in[11];
    const float* b2      = (const float*)d_in[12];
    const float* ln2g    = (const float*)d_in[13];
    const float* ln2b    = (const float*)d_in[14];
    const float* tw      = (const float*)d_in[15];
    const float* tb      = (const float*)d_in[16];
    const float* table   = (const float*)d_in[17];
    float* out = (float*)d_out;

    float *qkv, *ctx, *tmp, *y, *hid, *wr, *mp, *ue;
    cudaGetSymbolAddress((void**)&qkv, g_qkv);
    cudaGetSymbolAddress((void**)&ctx, g_ctx);
    cudaGetSymbolAddress((void**)&tmp, g_tmp);
    cudaGetSymbolAddress((void**)&y,   g_y);
    cudaGetSymbolAddress((void**)&hid, g_hid);
    cudaGetSymbolAddress((void**)&wr,  g_wr);
    cudaGetSymbolAddress((void**)&mp,  g_mp);
    cudaGetSymbolAddress((void**)&ue,  g_ue);

    float* wqkv_r = wr;                 // 3,145,728
    float* wo_r   = wr + 3145728;       // 1,048,576
    float* w1_r   = wr + 4194304;       // 4,194,304
    float* w2_r   = wr + 8388608;       // 4,194,304
    float* xr     = hid;                // rounded+permuted X (hid free until step 7)

    const int smem = NSTAGE * STAGE_F * 2 * sizeof(float);   // 98,304 B
    cudaFuncSetAttribute(mma_gemm, cudaFuncAttributeMaxDynamicSharedMemorySize, smem);

    // 0. round+permute X and all weights (counts in float8 units)
    round_perm_multi<<<8192, 256>>>(
        X,    xr,     (MROWS*WID)/8,
        Wqkv, wqkv_r, (3072*1024)/8,
        Wo,   wo_r,   (1024*1024)/8,
        W1,   w1_r,   (4096*1024)/8,
        W2,   w2_r,   (1024*4096)/8);

    // 1. QKV (round + permute output cols -> attention reads permuted d)
    mma_gemm<<<dim3(3072/BN, MROWS/BM), 128, smem>>>(xr, wqkv_r, bqkv, qkv, MROWS, 3072, 1024, 6);
    // 2. attention (ctx cols inherit permuted d-labels, rounded)
    attn_mma_kernel<<<dim3(SEQ/128, BATCH*HEADS), 256>>>(qkv, ctx);
    // 3. proj
    mma_gemm<<<dim3(WID/BN, MROWS/BM), 128, smem>>>(ctx, wo_r, bo, tmp, MROWS, WID, 1024, 0);
    // 4. y = LN(X + proj), plus rounded+permuted copy into ctx
    add_ln_kernel<<<MROWS, 256>>>(X, tmp, ln1g, ln1b, y, ctx);
    // 5. FF1 + GELU (round + permute -> FF2)
    mma_gemm<<<dim3(DFF/BN, MROWS/BM), 128, smem>>>(ctx, w1_r, b1, tmp, MROWS, DFF, 1024, 7);
    // 6. FF2
    mma_gemm<<<dim3(WID/BN, MROWS/BM), 128, smem>>>(tmp, w2_r, b2, ctx, MROWS, WID, 4096, 0);
    // 7. hidden = LN(y + FF2)
    add_ln_kernel<<<MROWS, 256>>>(y, ctx, ln2g, ln2b, hid, nullptr);
    // 8-10. topic path + final output
    maxpool_kernel<<<dim3(NGRP, BATCH), 256>>>(hid, in_ids, resp_ids, mp);
    topic_kernel<<<NGRP*BATCH, 256>>>(mp, tw, tb, table, ue);
    out_kernel<<<MROWS, 256>>>(X, in_ids, resp_ids, ue, out);
}